// round 4
// baseline (speedup 1.0000x reference)
#include <cuda_runtime.h>
#include <math.h>

// Problem constants
#define BATCH 4
#define SEQ   2048
#define DMODEL 1024
#define NHEAD 16
#define HD    64
#define MTOT  (BATCH * SEQ)   // 8192

// Scratch (allocation-free: __device__ globals)
__device__ float g_qkv[(size_t)BATCH * SEQ * 3 * DMODEL];  // [B,T,3D]  96 MB
__device__ float g_y  [(size_t)BATCH * SEQ * DMODEL];      // [B,T,D]   32 MB

// ---------------------------------------------------------------------------
// Tiled SGEMM with bias: C[M,N] = A[M,K] @ W[K,N] + bias[N]
// BM=BN=128, BK=16, TM=TN=8, 256 threads. All dims divisible (M=8192,
// N in {3072,1024}, K=1024) -> no bounds checks.
// ---------------------------------------------------------------------------
template <int BM, int BN, int BK, int TM, int TN>
__global__ void __launch_bounds__((BM / TM) * (BN / TN))
sgemm_bias(int M, int N, int K,
           const float* __restrict__ A,
           const float* __restrict__ W,
           const float* __restrict__ bias,
           float* __restrict__ C)
{
    constexpr int THREADS = (BM / TM) * (BN / TN);  // 256
    const int cRow = blockIdx.y;
    const int cCol = blockIdx.x;
    const int tid  = threadIdx.x;

    __shared__ float As[BK][BM + 4];   // +4 pad: break STS bank conflicts on transpose
    __shared__ float Bs[BK][BN];

    const int threadCol = tid % (BN / TN);   // 0..15
    const int threadRow = tid / (BN / TN);   // 0..15

    const float* Ab = A + (size_t)cRow * BM * K;
    const float* Wb = W + (size_t)cCol * BN;

    float acc[TM][TN];
    #pragma unroll
    for (int i = 0; i < TM; i++)
        #pragma unroll
        for (int j = 0; j < TN; j++) acc[i][j] = 0.0f;

    float regM[TM], regN[TN];

    // A-tile load map: one float4 per (row, 4-col) slot
    const int aRow = tid / (BK / 4);          // 0..63
    const int aCol = (tid % (BK / 4)) * 4;    // 0,4,8,12
    // B-tile load map
    const int bRow = tid / (BN / 4);          // 0..7
    const int bCol = (tid % (BN / 4)) * 4;    // 0..124

    for (int k0 = 0; k0 < K; k0 += BK) {
        // Load A tile (BM x BK), stored transposed into As[BK][BM]
        #pragma unroll
        for (int i = 0; i < BM; i += THREADS / (BK / 4)) {   // step 64
            float4 v = *(const float4*)&Ab[(size_t)(aRow + i) * K + k0 + aCol];
            As[aCol + 0][aRow + i] = v.x;
            As[aCol + 1][aRow + i] = v.y;
            As[aCol + 2][aRow + i] = v.z;
            As[aCol + 3][aRow + i] = v.w;
        }
        // Load B tile (BK x BN)
        #pragma unroll
        for (int i = 0; i < BK; i += THREADS / (BN / 4)) {   // step 8
            *(float4*)&Bs[bRow + i][bCol] =
                *(const float4*)&Wb[(size_t)(k0 + bRow + i) * N + bCol];
        }
        __syncthreads();

        #pragma unroll
        for (int k = 0; k < BK; k++) {
            #pragma unroll
            for (int i = 0; i < TM; i++) regM[i] = As[k][threadRow * TM + i];
            #pragma unroll
            for (int j = 0; j < TN; j++) regN[j] = Bs[k][threadCol * TN + j];
            #pragma unroll
            for (int i = 0; i < TM; i++)
                #pragma unroll
                for (int j = 0; j < TN; j++)
                    acc[i][j] += regM[i] * regN[j];
        }
        __syncthreads();
    }

    // Epilogue: add bias, vectorized store
    #pragma unroll
    for (int i = 0; i < TM; i++) {
        const int r = cRow * BM + threadRow * TM + i;
        #pragma unroll
        for (int j = 0; j < TN; j += 4) {
            const int c = cCol * BN + threadCol * TN + j;
            float4 bv = *(const float4*)&bias[c];
            float4 o;
            o.x = acc[i][j + 0] + bv.x;
            o.y = acc[i][j + 1] + bv.y;
            o.z = acc[i][j + 2] + bv.z;
            o.w = acc[i][j + 3] + bv.w;
            *(float4*)&C[(size_t)r * N + c] = o;
        }
    }
}

// ---------------------------------------------------------------------------
// Flash attention (no mask), fp32 online softmax.
// Grid: (SEQ/256, NHEAD, BATCH). 256 threads/block, 1 thread = 1 query row.
// K/V tiles of BC=32 rows staged in shared; q / acc / scores in registers.
// qkv layout: [(b*SEQ + t) * 3*DMODEL + s*DMODEL + h*HD + e]
// ---------------------------------------------------------------------------
#define BC 32

__global__ void __launch_bounds__(256, 1)
attn_kernel(const float* __restrict__ qkv, float* __restrict__ y)
{
    const int b   = blockIdx.z;
    const int h   = blockIdx.y;
    const int tid = threadIdx.x;
    const int qr  = blockIdx.x * 256 + tid;   // query row within [0, SEQ)

    __shared__ float Ks[BC][HD];
    __shared__ float Vs[BC][HD];

    const float scale = 0.125f;   // 1/sqrt(64)

    // Load q row into registers, pre-scaled
    float q[HD];
    {
        const float* qp = qkv + ((size_t)(b * SEQ + qr)) * (3 * DMODEL) + h * HD;
        #pragma unroll
        for (int e = 0; e < HD; e += 4) {
            float4 v = *(const float4*)&qp[e];
            q[e + 0] = v.x * scale;
            q[e + 1] = v.y * scale;
            q[e + 2] = v.z * scale;
            q[e + 3] = v.w * scale;
        }
    }

    float acc[HD];
    #pragma unroll
    for (int e = 0; e < HD; e++) acc[e] = 0.0f;
    float m = -1e30f;
    float l = 0.0f;

    // Tile load mapping: BC*HD = 2048 floats = 512 float4; 2 per thread
    const int r0 = tid >> 4;           // 0..15
    const int c0 = (tid & 15) * 4;     // 0..60

    for (int k0 = 0; k0 < SEQ; k0 += BC) {
        __syncthreads();
        {
            const size_t kbase = ((size_t)(b * SEQ + k0)) * (3 * DMODEL)
                               + DMODEL + h * HD;          // K at s=1
            // K rows r0 and r0+16
            *(float4*)&Ks[r0][c0] =
                *(const float4*)&qkv[kbase + (size_t)r0 * (3 * DMODEL) + c0];
            *(float4*)&Ks[r0 + 16][c0] =
                *(const float4*)&qkv[kbase + (size_t)(r0 + 16) * (3 * DMODEL) + c0];
            // V rows (offset +DMODEL more: s=2)
            *(float4*)&Vs[r0][c0] =
                *(const float4*)&qkv[kbase + DMODEL + (size_t)r0 * (3 * DMODEL) + c0];
            *(float4*)&Vs[r0 + 16][c0] =
                *(const float4*)&qkv[kbase + DMODEL + (size_t)(r0 + 16) * (3 * DMODEL) + c0];
        }
        __syncthreads();

        // S = q . K^T for this tile (broadcast LDS.128 reads)
        float s[BC];
        float mt = m;
        #pragma unroll
        for (int j = 0; j < BC; j++) {
            float sj = 0.0f;
            const float4* kp = (const float4*)Ks[j];
            #pragma unroll
            for (int e = 0; e < HD / 4; e++) {
                float4 kv = kp[e];
                sj += q[e * 4 + 0] * kv.x;
                sj += q[e * 4 + 1] * kv.y;
                sj += q[e * 4 + 2] * kv.z;
                sj += q[e * 4 + 3] * kv.w;
            }
            s[j] = sj;
            mt = fmaxf(mt, sj);
        }

        // Online softmax rescale
        const float alpha = __expf(m - mt);
        m = mt;
        l *= alpha;
        #pragma unroll
        for (int e = 0; e < HD; e++) acc[e] *= alpha;

        // acc += p_j * V[j]
        #pragma unroll
        for (int j = 0; j < BC; j++) {
            const float p = __expf(s[j] - mt);
            l += p;
            const float4* vp = (const float4*)Vs[j];
            #pragma unroll
            for (int e = 0; e < HD / 4; e++) {
                float4 vv = vp[e];
                acc[e * 4 + 0] += p * vv.x;
                acc[e * 4 + 1] += p * vv.y;
                acc[e * 4 + 2] += p * vv.z;
                acc[e * 4 + 3] += p * vv.w;
            }
        }
    }

    // Normalize and write to y[B,T,D] (head-interleaved layout for proj GEMM)
    const float inv = 1.0f / l;
    float* yp = y + ((size_t)(b * SEQ + qr)) * DMODEL + h * HD;
    #pragma unroll
    for (int e = 0; e < HD; e += 4) {
        float4 o;
        o.x = acc[e + 0] * inv;
        o.y = acc[e + 1] * inv;
        o.z = acc[e + 2] * inv;
        o.w = acc[e + 3] * inv;
        *(float4*)&yp[e] = o;
    }
}

// ---------------------------------------------------------------------------
// Launch
// ---------------------------------------------------------------------------
extern "C" void kernel_launch(void* const* d_in, const int* in_sizes, int n_in,
                              void* d_out, int out_size)
{
    const float* x     = (const float*)d_in[0];
    const float* Wqkv  = (const float*)d_in[1];
    const float* bqkv  = (const float*)d_in[2];
    const float* Wproj = (const float*)d_in[3];
    const float* bproj = (const float*)d_in[4];
    float* out = (float*)d_out;

    float* qkv = nullptr;
    float* y   = nullptr;
    cudaGetSymbolAddress((void**)&qkv, g_qkv);   // no allocation, capture-safe
    cudaGetSymbolAddress((void**)&y,   g_y);

    dim3 block(256);

    // 1) QKV projection: [8192,1024] @ [1024,3072] + b
    sgemm_bias<128, 128, 16, 8, 8>
        <<<dim3(3 * DMODEL / 128, MTOT / 128), block>>>(
            MTOT, 3 * DMODEL, DMODEL, x, Wqkv, bqkv, qkv);

    // 2) Flash attention -> y [B,T,D]
    attn_kernel<<<dim3(SEQ / 256, NHEAD, BATCH), block>>>(qkv, y);

    // 3) Output projection: [8192,1024] @ [1024,1024] + b
    sgemm_bias<128, 128, 16, 8, 8>
        <<<dim3(DMODEL / 128, MTOT / 128), block>>>(
            MTOT, DMODEL, DMODEL, y, Wproj, bproj, out);
}

// round 5
// speedup vs baseline: 3.5510x; 3.5510x over previous
#include <cuda_runtime.h>
#include <math.h>
#include <stdint.h>

// Problem constants
#define BATCH  4
#define SEQ    2048
#define DMODEL 1024
#define NHEAD  16
#define HD     64
#define MTOT   (BATCH * SEQ)   // 8192

// Scratch (allocation-free: __device__ globals)
__device__ float g_qkv[(size_t)BATCH * SEQ * 3 * DMODEL];  // [B,T,3D]  96 MB
__device__ float g_y  [(size_t)BATCH * SEQ * DMODEL];      // [B,T,D]   32 MB

// ---------------------------------------------------------------------------
// Helpers: tf32 convert (round-to-nearest) + m16n8k8 tf32 MMA
// ---------------------------------------------------------------------------
__device__ __forceinline__ uint32_t f2tf(float f) {
    uint32_t u;
    asm("cvt.rna.tf32.f32 %0, %1;" : "=r"(u) : "f"(f));
    return u;
}
__device__ __forceinline__ float f2tf_f(float f) { return __uint_as_float(f2tf(f)); }

__device__ __forceinline__ void mma8(float* c, const uint32_t* a,
                                     uint32_t b0, uint32_t b1) {
    asm volatile(
        "mma.sync.aligned.m16n8k8.row.col.f32.tf32.tf32.f32 "
        "{%0,%1,%2,%3},{%4,%5,%6,%7},{%8,%9},{%0,%1,%2,%3};\n"
        : "+f"(c[0]), "+f"(c[1]), "+f"(c[2]), "+f"(c[3])
        : "r"(a[0]), "r"(a[1]), "r"(a[2]), "r"(a[3]), "r"(b0), "r"(b1));
}

// ---------------------------------------------------------------------------
// tf32 tensor-core GEMM + bias: C[M,N] = A[M,K] @ W[K,N] + bias[N]
// BM=BN=128, BK=32. 8 warps (2x4), warp tile 64x32, m16n8k8 frags.
// As stride 36 (=4 mod 32), Bs stride 136 (=8 mod 32): conflict-free frag LDS.
// ---------------------------------------------------------------------------
#define AS_S 36
#define BS_S 136

__global__ void __launch_bounds__(256, 1)
gemm_tf32(int M, int N, int K,
          const float* __restrict__ A,
          const float* __restrict__ W,
          const float* __restrict__ bias,
          float* __restrict__ C)
{
    __shared__ float As[128 * AS_S];
    __shared__ float Bs[32 * BS_S];

    const int tid  = threadIdx.x;
    const int wid  = tid >> 5;
    const int lane = tid & 31;
    const int gid  = lane >> 2;   // 0..7
    const int tig  = lane & 3;    // 0..3
    const int wm   = wid >> 2;    // 0..1 -> 64 rows
    const int wn   = wid & 3;     // 0..3 -> 32 cols

    const float* Ab = A + (size_t)blockIdx.y * 128 * K;
    const float* Wb = W + (size_t)blockIdx.x * 128;

    float c[4][4][4];
    #pragma unroll
    for (int i = 0; i < 4; i++)
        #pragma unroll
        for (int j = 0; j < 4; j++)
            #pragma unroll
            for (int r = 0; r < 4; r++) c[i][j][r] = 0.0f;

    // Global-load maps
    const int arow = tid >> 3;          // 0..31 (A rows, +i*32)
    const int acol = (tid & 7) * 4;     // 0..28
    const int brow = tid >> 5;          // 0..7  (B rows, +i*8)
    const int bcol = (tid & 31) * 4;    // 0..124

    float4 pa[4], pb[4];

    // initial prefetch k0 = 0
    #pragma unroll
    for (int i = 0; i < 4; i++) {
        pa[i] = *(const float4*)&Ab[(size_t)(arow + i * 32) * K + acol];
        pb[i] = *(const float4*)&Wb[(size_t)(brow + i * 8) * N + bcol];
    }

    for (int k0 = 0; k0 < K; k0 += 32) {
        // stage prefetched tile into smem with tf32 conversion
        #pragma unroll
        for (int i = 0; i < 4; i++) {
            float4 v = pa[i];
            float4 w;
            w.x = f2tf_f(v.x); w.y = f2tf_f(v.y);
            w.z = f2tf_f(v.z); w.w = f2tf_f(v.w);
            *(float4*)&As[(arow + i * 32) * AS_S + acol] = w;
            float4 u = pb[i];
            float4 t;
            t.x = f2tf_f(u.x); t.y = f2tf_f(u.y);
            t.z = f2tf_f(u.z); t.w = f2tf_f(u.w);
            *(float4*)&Bs[(brow + i * 8) * BS_S + bcol] = t;
        }
        __syncthreads();

        // prefetch next tile while computing
        if (k0 + 32 < K) {
            #pragma unroll
            for (int i = 0; i < 4; i++) {
                pa[i] = *(const float4*)&Ab[(size_t)(arow + i * 32) * K + k0 + 32 + acol];
                pb[i] = *(const float4*)&Wb[(size_t)(k0 + 32 + brow + i * 8) * N + bcol];
            }
        }

        #pragma unroll
        for (int kk = 0; kk < 32; kk += 8) {
            uint32_t af[4][4];
            #pragma unroll
            for (int mt = 0; mt < 4; mt++) {
                const int r = wm * 64 + mt * 16 + gid;
                af[mt][0] = __float_as_uint(As[(r    ) * AS_S + kk + tig    ]);
                af[mt][1] = __float_as_uint(As[(r + 8) * AS_S + kk + tig    ]);
                af[mt][2] = __float_as_uint(As[(r    ) * AS_S + kk + tig + 4]);
                af[mt][3] = __float_as_uint(As[(r + 8) * AS_S + kk + tig + 4]);
            }
            uint32_t bf[4][2];
            #pragma unroll
            for (int nt = 0; nt < 4; nt++) {
                const int col = wn * 32 + nt * 8 + gid;
                bf[nt][0] = __float_as_uint(Bs[(kk + tig    ) * BS_S + col]);
                bf[nt][1] = __float_as_uint(Bs[(kk + tig + 4) * BS_S + col]);
            }
            #pragma unroll
            for (int mt = 0; mt < 4; mt++)
                #pragma unroll
                for (int nt = 0; nt < 4; nt++)
                    mma8(c[mt][nt], af[mt], bf[nt][0], bf[nt][1]);
        }
        __syncthreads();
    }

    // Epilogue: bias + store
    #pragma unroll
    for (int mt = 0; mt < 4; mt++) {
        const int r = blockIdx.y * 128 + wm * 64 + mt * 16 + gid;
        #pragma unroll
        for (int nt = 0; nt < 4; nt++) {
            const int col = blockIdx.x * 128 + wn * 32 + nt * 8 + 2 * tig;
            float2 bv = *(const float2*)&bias[col];
            float2 o0, o1;
            o0.x = c[mt][nt][0] + bv.x; o0.y = c[mt][nt][1] + bv.y;
            o1.x = c[mt][nt][2] + bv.x; o1.y = c[mt][nt][3] + bv.y;
            *(float2*)&C[(size_t)(r    ) * N + col] = o0;
            *(float2*)&C[(size_t)(r + 8) * N + col] = o1;
        }
    }
}

// ---------------------------------------------------------------------------
// Tensor-core flash attention (tf32). Br=64 query rows per block, 4 warps,
// each warp owns 16 q-rows. Bc=64 key tile. S=QK^T and P@V on m16n8k8 MMA,
// online softmax in C-fragment layout with quad shuffles.
// SKP buffer is reused: Q staging -> K tile -> P tile (sync-separated).
// Strides: SKP 68 (=4 mod 32), Vs 72 (=8 mod 32): conflict-free frag LDS.
// ---------------------------------------------------------------------------
#define SK_S 68
#define VS_S 72

__global__ void __launch_bounds__(128, 1)
attn_tf32(const float* __restrict__ qkv, float* __restrict__ y)
{
    __shared__ float SKP[64 * SK_S];   // Q stage / K tile / P tile
    __shared__ float Vs [64 * VS_S];   // V tile

    const int b   = blockIdx.z;
    const int h   = blockIdx.y;
    const int q0  = blockIdx.x * 64;
    const int tid  = threadIdx.x;
    const int wid  = tid >> 5;
    const int lane = tid & 31;
    const int gid  = lane >> 2;
    const int tig  = lane & 3;

    const float scale = 0.125f;   // 1/sqrt(64)

    // Stage Q tile (pre-scaled, tf32) into SKP
    {
        const int row = tid >> 4;          // 0..7
        const int cb  = (tid & 15) * 4;    // 0..60
        #pragma unroll
        for (int i = 0; i < 8; i++) {
            const int r = row + i * 8;
            const float* p = qkv + ((size_t)(b * SEQ + q0 + r)) * (3 * DMODEL)
                           + h * HD + cb;
            float4 v = *(const float4*)p;
            float4 w;
            w.x = f2tf_f(v.x * scale); w.y = f2tf_f(v.y * scale);
            w.z = f2tf_f(v.z * scale); w.w = f2tf_f(v.w * scale);
            *(float4*)&SKP[r * SK_S + cb] = w;
        }
    }
    __syncthreads();

    // Q fragments (registers, resident for whole KV loop)
    uint32_t qa[8][4];
    {
        const int r0 = wid * 16 + gid;
        #pragma unroll
        for (int kk = 0; kk < 8; kk++) {
            qa[kk][0] = __float_as_uint(SKP[(r0    ) * SK_S + kk * 8 + tig    ]);
            qa[kk][1] = __float_as_uint(SKP[(r0 + 8) * SK_S + kk * 8 + tig    ]);
            qa[kk][2] = __float_as_uint(SKP[(r0    ) * SK_S + kk * 8 + tig + 4]);
            qa[kk][3] = __float_as_uint(SKP[(r0 + 8) * SK_S + kk * 8 + tig + 4]);
        }
    }
    __syncthreads();

    float o[8][4];
    #pragma unroll
    for (int n = 0; n < 8; n++)
        #pragma unroll
        for (int j = 0; j < 4; j++) o[n][j] = 0.0f;
    float m0 = -1e30f, m1 = -1e30f, l0 = 0.0f, l1 = 0.0f;

    const int srow = tid >> 4;
    const int scb  = (tid & 15) * 4;
    const int pr   = wid * 16 + gid;   // this thread's q-row (frag row 0)

    for (int kt = 0; kt < SEQ; kt += 64) {
        // ---- stage K, V tiles (tf32) ----
        #pragma unroll
        for (int i = 0; i < 8; i++) {
            const int r = srow + i * 8;
            const size_t base = ((size_t)(b * SEQ + kt + r)) * (3 * DMODEL)
                              + h * HD + scb;
            float4 kv = *(const float4*)&qkv[base + DMODEL];
            float4 vv = *(const float4*)&qkv[base + 2 * DMODEL];
            float4 kw, vw;
            kw.x = f2tf_f(kv.x); kw.y = f2tf_f(kv.y);
            kw.z = f2tf_f(kv.z); kw.w = f2tf_f(kv.w);
            vw.x = f2tf_f(vv.x); vw.y = f2tf_f(vv.y);
            vw.z = f2tf_f(vv.z); vw.w = f2tf_f(vv.w);
            *(float4*)&SKP[r * SK_S + scb] = kw;
            *(float4*)&Vs [r * VS_S + scb] = vw;
        }
        __syncthreads();

        // ---- S = Q K^T (warp rows x 64 keys) ----
        float s[8][4];
        #pragma unroll
        for (int n = 0; n < 8; n++)
            #pragma unroll
            for (int j = 0; j < 4; j++) s[n][j] = 0.0f;
        #pragma unroll
        for (int kk = 0; kk < 8; kk++) {
            #pragma unroll
            for (int n = 0; n < 8; n++) {
                uint32_t b0 = __float_as_uint(SKP[(n * 8 + gid) * SK_S + kk * 8 + tig    ]);
                uint32_t b1 = __float_as_uint(SKP[(n * 8 + gid) * SK_S + kk * 8 + tig + 4]);
                mma8(s[n], qa[kk], b0, b1);
            }
        }
        __syncthreads();   // K tile consumed by all warps; SKP free for P

        // ---- online softmax (rows pr and pr+8) ----
        float mx0 = -1e30f, mx1 = -1e30f;
        #pragma unroll
        for (int n = 0; n < 8; n++) {
            mx0 = fmaxf(mx0, fmaxf(s[n][0], s[n][1]));
            mx1 = fmaxf(mx1, fmaxf(s[n][2], s[n][3]));
        }
        mx0 = fmaxf(mx0, __shfl_xor_sync(0xffffffffu, mx0, 1));
        mx0 = fmaxf(mx0, __shfl_xor_sync(0xffffffffu, mx0, 2));
        mx1 = fmaxf(mx1, __shfl_xor_sync(0xffffffffu, mx1, 1));
        mx1 = fmaxf(mx1, __shfl_xor_sync(0xffffffffu, mx1, 2));
        const float mn0 = fmaxf(m0, mx0);
        const float mn1 = fmaxf(m1, mx1);
        const float al0 = __expf(m0 - mn0);
        const float al1 = __expf(m1 - mn1);
        m0 = mn0; m1 = mn1;

        float sum0 = 0.0f, sum1 = 0.0f;
        #pragma unroll
        for (int n = 0; n < 8; n++) {
            s[n][0] = __expf(s[n][0] - mn0); sum0 += s[n][0];
            s[n][1] = __expf(s[n][1] - mn0); sum0 += s[n][1];
            s[n][2] = __expf(s[n][2] - mn1); sum1 += s[n][2];
            s[n][3] = __expf(s[n][3] - mn1); sum1 += s[n][3];
        }
        sum0 += __shfl_xor_sync(0xffffffffu, sum0, 1);
        sum0 += __shfl_xor_sync(0xffffffffu, sum0, 2);
        sum1 += __shfl_xor_sync(0xffffffffu, sum1, 1);
        sum1 += __shfl_xor_sync(0xffffffffu, sum1, 2);
        l0 = l0 * al0 + sum0;
        l1 = l1 * al1 + sum1;

        #pragma unroll
        for (int n = 0; n < 8; n++) {
            o[n][0] *= al0; o[n][1] *= al0;
            o[n][2] *= al1; o[n][3] *= al1;
        }

        // ---- P -> smem (tf32) ; own warp's rows only ----
        #pragma unroll
        for (int n = 0; n < 8; n++) {
            SKP[(pr    ) * SK_S + n * 8 + 2 * tig    ] = f2tf_f(s[n][0]);
            SKP[(pr    ) * SK_S + n * 8 + 2 * tig + 1] = f2tf_f(s[n][1]);
            SKP[(pr + 8) * SK_S + n * 8 + 2 * tig    ] = f2tf_f(s[n][2]);
            SKP[(pr + 8) * SK_S + n * 8 + 2 * tig + 1] = f2tf_f(s[n][3]);
        }
        __syncwarp();

        // ---- O += P @ V ----
        #pragma unroll
        for (int kk = 0; kk < 8; kk++) {
            uint32_t pa[4];
            pa[0] = __float_as_uint(SKP[(pr    ) * SK_S + kk * 8 + tig    ]);
            pa[1] = __float_as_uint(SKP[(pr + 8) * SK_S + kk * 8 + tig    ]);
            pa[2] = __float_as_uint(SKP[(pr    ) * SK_S + kk * 8 + tig + 4]);
            pa[3] = __float_as_uint(SKP[(pr + 8) * SK_S + kk * 8 + tig + 4]);
            #pragma unroll
            for (int n = 0; n < 8; n++) {
                uint32_t b0 = __float_as_uint(Vs[(kk * 8 + tig    ) * VS_S + n * 8 + gid]);
                uint32_t b1 = __float_as_uint(Vs[(kk * 8 + tig + 4) * VS_S + n * 8 + gid]);
                mma8(o[n], pa, b0, b1);
            }
        }
        __syncthreads();   // protect SKP/Vs before next stage
    }

    // ---- normalize + write y[B,T,D] ----
    const float i0 = 1.0f / l0;
    const float i1 = 1.0f / l1;
    const int r = q0 + pr;
    float* yp = y + ((size_t)(b * SEQ + r)) * DMODEL + h * HD;
    #pragma unroll
    for (int n = 0; n < 8; n++) {
        const int cc = n * 8 + 2 * tig;
        float2 w0, w1;
        w0.x = o[n][0] * i0; w0.y = o[n][1] * i0;
        w1.x = o[n][2] * i1; w1.y = o[n][3] * i1;
        *(float2*)&yp[cc]               = w0;
        *(float2*)&yp[8 * DMODEL + cc]  = w1;
    }
}

// ---------------------------------------------------------------------------
// Launch
// ---------------------------------------------------------------------------
extern "C" void kernel_launch(void* const* d_in, const int* in_sizes, int n_in,
                              void* d_out, int out_size)
{
    const float* x     = (const float*)d_in[0];
    const float* Wqkv  = (const float*)d_in[1];
    const float* bqkv  = (const float*)d_in[2];
    const float* Wproj = (const float*)d_in[3];
    const float* bproj = (const float*)d_in[4];
    float* out = (float*)d_out;

    float* qkv = nullptr;
    float* y   = nullptr;
    cudaGetSymbolAddress((void**)&qkv, g_qkv);
    cudaGetSymbolAddress((void**)&y,   g_y);

    // 1) QKV projection: [8192,1024] @ [1024,3072] + b
    gemm_tf32<<<dim3(3 * DMODEL / 128, MTOT / 128), 256>>>(
        MTOT, 3 * DMODEL, DMODEL, x, Wqkv, bqkv, qkv);

    // 2) Flash attention (tensor core) -> y [B,T,D]
    attn_tf32<<<dim3(SEQ / 64, NHEAD, BATCH), 128>>>(qkv, y);

    // 3) Output projection: [8192,1024] @ [1024,1024] + b
    gemm_tf32<<<dim3(DMODEL / 128, MTOT / 128), 256>>>(
        MTOT, DMODEL, DMODEL, y, Wproj, bproj, out);
}

// round 6
// speedup vs baseline: 3.7729x; 1.0625x over previous
#include <cuda_runtime.h>
#include <math.h>
#include <stdint.h>

// Problem constants
#define BATCH  4
#define SEQ    2048
#define DMODEL 1024
#define NHEAD  16
#define HD     64
#define MTOT   (BATCH * SEQ)   // 8192

// Scratch (allocation-free: __device__ globals)
__device__ float g_qkv[(size_t)BATCH * SEQ * 3 * DMODEL];   // [B,T,3D] tf32-rounded
__device__ float g_y  [(size_t)BATCH * SEQ * DMODEL];       // [B,T,D]  tf32-rounded
__device__ float g_x  [(size_t)MTOT * DMODEL];              // x  tf32-rounded
__device__ float g_wq [(size_t)DMODEL * 3 * DMODEL];        // Wqkv tf32-rounded
__device__ float g_wp [(size_t)DMODEL * DMODEL];            // Wproj tf32-rounded

// ---------------------------------------------------------------------------
// Helpers
// ---------------------------------------------------------------------------
__device__ __forceinline__ uint32_t f2tf(float f) {
    uint32_t u;
    asm("cvt.rna.tf32.f32 %0, %1;" : "=r"(u) : "f"(f));
    return u;
}
__device__ __forceinline__ float f2tf_f(float f) { return __uint_as_float(f2tf(f)); }

__device__ __forceinline__ void mma8(float* c, const uint32_t* a,
                                     uint32_t b0, uint32_t b1) {
    asm volatile(
        "mma.sync.aligned.m16n8k8.row.col.f32.tf32.tf32.f32 "
        "{%0,%1,%2,%3},{%4,%5,%6,%7},{%8,%9},{%0,%1,%2,%3};\n"
        : "+f"(c[0]), "+f"(c[1]), "+f"(c[2]), "+f"(c[3])
        : "r"(a[0]), "r"(a[1]), "r"(a[2]), "r"(a[3]), "r"(b0), "r"(b1));
}

__device__ __forceinline__ void cp_async16(uint32_t smem_dst, const void* gsrc) {
    asm volatile("cp.async.cg.shared.global [%0], [%1], 16;\n"
                 :: "r"(smem_dst), "l"(gsrc));
}
__device__ __forceinline__ void cp_commit() {
    asm volatile("cp.async.commit_group;\n");
}
template <int N>
__device__ __forceinline__ void cp_wait() {
    asm volatile("cp.async.wait_group %0;\n" :: "n"(N));
}

// ---------------------------------------------------------------------------
// Pre-round to tf32 grid (one-shot elementwise pass)
// ---------------------------------------------------------------------------
__global__ void round_tf32(const float* __restrict__ in, float* __restrict__ out,
                           int n4)
{
    int i = blockIdx.x * blockDim.x + threadIdx.x;
    if (i < n4) {
        float4 v = ((const float4*)in)[i];
        float4 w;
        w.x = f2tf_f(v.x); w.y = f2tf_f(v.y);
        w.z = f2tf_f(v.z); w.w = f2tf_f(v.w);
        ((float4*)out)[i] = w;
    }
}

// ---------------------------------------------------------------------------
// tf32 tensor-core GEMM + bias, cp.async 3-stage pipeline.
// Inputs A, W must be tf32-rounded already. C = A@W + bias, optionally
// tf32-rounded on output (ROUND).
// BM=BN=128, BK=32, 8 warps (2x4), warp tile 64x32, m16n8k8 frags.
// As stride 36 (=4 mod 32), Bs stride 136 (=8 mod 32): conflict-free LDS.
// ---------------------------------------------------------------------------
#define AS_S 36
#define BS_S 136
#define G_STAGES 3
#define A_STG (128 * AS_S)       // floats per A stage
#define B_STG (32 * BS_S)        // floats per B stage
#define GEMM_SMEM ((G_STAGES * (A_STG + B_STG)) * 4)   // 107520 B

template <bool ROUND>
__global__ void __launch_bounds__(256, 1)
gemm_tf32(int M, int N, int K,
          const float* __restrict__ A,
          const float* __restrict__ W,
          const float* __restrict__ bias,
          float* __restrict__ C)
{
    extern __shared__ float dynsmem[];
    float* As = dynsmem;
    float* Bs = dynsmem + G_STAGES * A_STG;
    const uint32_t as_u32 = (uint32_t)__cvta_generic_to_shared(As);
    const uint32_t bs_u32 = (uint32_t)__cvta_generic_to_shared(Bs);

    const int tid  = threadIdx.x;
    const int wid  = tid >> 5;
    const int lane = tid & 31;
    const int gid  = lane >> 2;
    const int tig  = lane & 3;
    const int wm   = wid >> 2;
    const int wn   = wid & 3;

    const float* Ab = A + (size_t)blockIdx.y * 128 * K;
    const float* Wb = W + (size_t)blockIdx.x * 128;

    // Global-load maps (4 x 16B chunks each for A and B per stage)
    const int arow = tid >> 3;          // 0..31 (+i*32)
    const int acol = (tid & 7) * 4;     // 0..28
    const int brow = tid >> 5;          // 0..7  (+i*8)
    const int bcol = (tid & 31) * 4;    // 0..124

    float c[4][4][4];
    #pragma unroll
    for (int i = 0; i < 4; i++)
        #pragma unroll
        for (int j = 0; j < 4; j++)
            #pragma unroll
            for (int r = 0; r < 4; r++) c[i][j][r] = 0.0f;

    const int T = K / 32;

    auto issue = [&](int kt, int s) {
        const float* Asrc = Ab + (size_t)arow * K + kt * 32 + acol;
        uint32_t ad = as_u32 + (uint32_t)(s * A_STG + arow * AS_S + acol) * 4;
        #pragma unroll
        for (int i = 0; i < 4; i++)
            cp_async16(ad + (uint32_t)(i * 32 * AS_S) * 4, Asrc + (size_t)i * 32 * K);
        const float* Bsrc = Wb + (size_t)(kt * 32 + brow) * N + bcol;
        uint32_t bd = bs_u32 + (uint32_t)(s * B_STG + brow * BS_S + bcol) * 4;
        #pragma unroll
        for (int i = 0; i < 4; i++)
            cp_async16(bd + (uint32_t)(i * 8 * BS_S) * 4, Bsrc + (size_t)i * 8 * N);
        cp_commit();
    };

    issue(0, 0);
    issue(1, 1);

    for (int t = 0; t < T; t++) {
        cp_wait<G_STAGES - 2>();   // tile t landed (this thread)
        __syncthreads();           // all threads' copies visible; tile t-1 compute done
        if (t + 2 < T) issue(t + 2, (t + 2) % G_STAGES);

        const float* as = As + (t % G_STAGES) * A_STG;
        const float* bs = Bs + (t % G_STAGES) * B_STG;

        #pragma unroll
        for (int kk = 0; kk < 32; kk += 8) {
            uint32_t af[4][4];
            #pragma unroll
            for (int mt = 0; mt < 4; mt++) {
                const int r = wm * 64 + mt * 16 + gid;
                af[mt][0] = __float_as_uint(as[(r    ) * AS_S + kk + tig    ]);
                af[mt][1] = __float_as_uint(as[(r + 8) * AS_S + kk + tig    ]);
                af[mt][2] = __float_as_uint(as[(r    ) * AS_S + kk + tig + 4]);
                af[mt][3] = __float_as_uint(as[(r + 8) * AS_S + kk + tig + 4]);
            }
            uint32_t bf[4][2];
            #pragma unroll
            for (int nt = 0; nt < 4; nt++) {
                const int col = wn * 32 + nt * 8 + gid;
                bf[nt][0] = __float_as_uint(bs[(kk + tig    ) * BS_S + col]);
                bf[nt][1] = __float_as_uint(bs[(kk + tig + 4) * BS_S + col]);
            }
            #pragma unroll
            for (int mt = 0; mt < 4; mt++)
                #pragma unroll
                for (int nt = 0; nt < 4; nt++)
                    mma8(c[mt][nt], af[mt], bf[nt][0], bf[nt][1]);
        }
    }

    // Epilogue: bias + (optional round) + store
    #pragma unroll
    for (int mt = 0; mt < 4; mt++) {
        const int r = blockIdx.y * 128 + wm * 64 + mt * 16 + gid;
        #pragma unroll
        for (int nt = 0; nt < 4; nt++) {
            const int col = blockIdx.x * 128 + wn * 32 + nt * 8 + 2 * tig;
            float2 bv = *(const float2*)&bias[col];
            float2 o0, o1;
            if (ROUND) {
                o0.x = f2tf_f(c[mt][nt][0] + bv.x); o0.y = f2tf_f(c[mt][nt][1] + bv.y);
                o1.x = f2tf_f(c[mt][nt][2] + bv.x); o1.y = f2tf_f(c[mt][nt][3] + bv.y);
            } else {
                o0.x = c[mt][nt][0] + bv.x; o0.y = c[mt][nt][1] + bv.y;
                o1.x = c[mt][nt][2] + bv.x; o1.y = c[mt][nt][3] + bv.y;
            }
            *(float2*)&C[(size_t)(r    ) * N + col] = o0;
            *(float2*)&C[(size_t)(r + 8) * N + col] = o1;
        }
    }
}

// ---------------------------------------------------------------------------
// Tensor-core flash attention (tf32), cp.async double-buffered K/V.
// qkv must be tf32-rounded. Br=64, 4 warps (16 q-rows each), Bc=64.
// Layout (dynamic smem): K[2 stages, 64 x 68] | V[2 stages, 64 x 72] | P[64 x 68]
// ---------------------------------------------------------------------------
#define SK_S 68
#define VS_S 72
#define K_STG (64 * SK_S)
#define V_STG (64 * VS_S)
#define ATTN_SMEM ((2 * K_STG + 2 * V_STG + 64 * SK_S) * 4)   // 89088 B

__global__ void __launch_bounds__(128, 1)
attn_tf32(const float* __restrict__ qkv, float* __restrict__ y)
{
    extern __shared__ float dynsmem[];
    float* Ksm = dynsmem;
    float* Vsm = dynsmem + 2 * K_STG;
    float* Psm = dynsmem + 2 * K_STG + 2 * V_STG;
    const uint32_t k_u32 = (uint32_t)__cvta_generic_to_shared(Ksm);
    const uint32_t v_u32 = (uint32_t)__cvta_generic_to_shared(Vsm);

    const int b    = blockIdx.z;
    const int h    = blockIdx.y;
    const int q0   = blockIdx.x * 64;
    const int tid  = threadIdx.x;
    const int wid  = tid >> 5;
    const int lane = tid & 31;
    const int gid  = lane >> 2;
    const int tig  = lane & 3;

    const int srow = tid >> 4;          // 0..7 (+i*8)
    const int scb  = (tid & 15) * 4;    // 0..60
    const int pr   = wid * 16 + gid;    // this thread's q-row (frag row 0)

    auto issue_kv = [&](int kt, int s) {
        const size_t base = ((size_t)(b * SEQ + kt + srow)) * (3 * DMODEL)
                          + DMODEL + h * HD + scb;       // K (slot 1)
        uint32_t kd = k_u32 + (uint32_t)(s * K_STG + srow * SK_S + scb) * 4;
        uint32_t vd = v_u32 + (uint32_t)(s * V_STG + srow * VS_S + scb) * 4;
        #pragma unroll
        for (int i = 0; i < 8; i++) {
            const size_t go = base + (size_t)i * 8 * (3 * DMODEL);
            cp_async16(kd + (uint32_t)(i * 8 * SK_S) * 4, qkv + go);
            cp_async16(vd + (uint32_t)(i * 8 * VS_S) * 4, qkv + go + DMODEL);
        }
        cp_commit();
    };

    issue_kv(0, 0);   // overlap tile-0 K/V load with Q staging

    // Stage Q tile (pre-scaled; values already tf32-rounded, *0.125 exact)
    {
        #pragma unroll
        for (int i = 0; i < 8; i++) {
            const int r = srow + i * 8;
            const float* p = qkv + ((size_t)(b * SEQ + q0 + r)) * (3 * DMODEL)
                           + h * HD + scb;
            float4 v = *(const float4*)p;
            float4 w;
            w.x = v.x * 0.125f; w.y = v.y * 0.125f;
            w.z = v.z * 0.125f; w.w = v.w * 0.125f;
            *(float4*)&Psm[r * SK_S + scb] = w;
        }
    }
    __syncthreads();

    // Q fragments (registers, resident for whole KV loop)
    uint32_t qa[8][4];
    #pragma unroll
    for (int kk = 0; kk < 8; kk++) {
        qa[kk][0] = __float_as_uint(Psm[(pr    ) * SK_S + kk * 8 + tig    ]);
        qa[kk][1] = __float_as_uint(Psm[(pr + 8) * SK_S + kk * 8 + tig    ]);
        qa[kk][2] = __float_as_uint(Psm[(pr    ) * SK_S + kk * 8 + tig + 4]);
        qa[kk][3] = __float_as_uint(Psm[(pr + 8) * SK_S + kk * 8 + tig + 4]);
    }

    float o[8][4];
    #pragma unroll
    for (int n = 0; n < 8; n++)
        #pragma unroll
        for (int j = 0; j < 4; j++) o[n][j] = 0.0f;
    float m0 = -1e30f, m1 = -1e30f, l0 = 0.0f, l1 = 0.0f;

    for (int t = 0; t < SEQ / 64; t++) {
        cp_wait<0>();       // tile t K/V landed (this thread)
        __syncthreads();    // visible to all; prior tile's buffers free
        if (t + 1 < SEQ / 64) issue_kv((t + 1) * 64, (t + 1) & 1);

        const float* Ks = Ksm + (t & 1) * K_STG;
        const float* Vs = Vsm + (t & 1) * V_STG;

        // ---- S = Q K^T ----
        float s[8][4];
        #pragma unroll
        for (int n = 0; n < 8; n++)
            #pragma unroll
            for (int j = 0; j < 4; j++) s[n][j] = 0.0f;
        #pragma unroll
        for (int kk = 0; kk < 8; kk++) {
            #pragma unroll
            for (int n = 0; n < 8; n++) {
                uint32_t b0 = __float_as_uint(Ks[(n * 8 + gid) * SK_S + kk * 8 + tig    ]);
                uint32_t b1 = __float_as_uint(Ks[(n * 8 + gid) * SK_S + kk * 8 + tig + 4]);
                mma8(s[n], qa[kk], b0, b1);
            }
        }

        // ---- online softmax (rows pr, pr+8) ----
        float mx0 = -1e30f, mx1 = -1e30f;
        #pragma unroll
        for (int n = 0; n < 8; n++) {
            mx0 = fmaxf(mx0, fmaxf(s[n][0], s[n][1]));
            mx1 = fmaxf(mx1, fmaxf(s[n][2], s[n][3]));
        }
        mx0 = fmaxf(mx0, __shfl_xor_sync(0xffffffffu, mx0, 1));
        mx0 = fmaxf(mx0, __shfl_xor_sync(0xffffffffu, mx0, 2));
        mx1 = fmaxf(mx1, __shfl_xor_sync(0xffffffffu, mx1, 1));
        mx1 = fmaxf(mx1, __shfl_xor_sync(0xffffffffu, mx1, 2));
        const float mn0 = fmaxf(m0, mx0);
        const float mn1 = fmaxf(m1, mx1);
        const float al0 = __expf(m0 - mn0);
        const float al1 = __expf(m1 - mn1);
        m0 = mn0; m1 = mn1;

        float sum0 = 0.0f, sum1 = 0.0f;
        #pragma unroll
        for (int n = 0; n < 8; n++) {
            s[n][0] = __expf(s[n][0] - mn0); sum0 += s[n][0];
            s[n][1] = __expf(s[n][1] - mn0); sum0 += s[n][1];
            s[n][2] = __expf(s[n][2] - mn1); sum1 += s[n][2];
            s[n][3] = __expf(s[n][3] - mn1); sum1 += s[n][3];
        }
        sum0 += __shfl_xor_sync(0xffffffffu, sum0, 1);
        sum0 += __shfl_xor_sync(0xffffffffu, sum0, 2);
        sum1 += __shfl_xor_sync(0xffffffffu, sum1, 1);
        sum1 += __shfl_xor_sync(0xffffffffu, sum1, 2);
        l0 = l0 * al0 + sum0;
        l1 = l1 * al1 + sum1;

        #pragma unroll
        for (int n = 0; n < 8; n++) {
            o[n][0] *= al0; o[n][1] *= al0;
            o[n][2] *= al1; o[n][3] *= al1;
        }

        // ---- P -> smem (tf32-rounded); per-warp private rows ----
        #pragma unroll
        for (int n = 0; n < 8; n++) {
            Psm[(pr    ) * SK_S + n * 8 + 2 * tig    ] = f2tf_f(s[n][0]);
            Psm[(pr    ) * SK_S + n * 8 + 2 * tig + 1] = f2tf_f(s[n][1]);
            Psm[(pr + 8) * SK_S + n * 8 + 2 * tig    ] = f2tf_f(s[n][2]);
            Psm[(pr + 8) * SK_S + n * 8 + 2 * tig + 1] = f2tf_f(s[n][3]);
        }
        __syncwarp();

        // ---- O += P @ V ----
        #pragma unroll
        for (int kk = 0; kk < 8; kk++) {
            uint32_t pa[4];
            pa[0] = __float_as_uint(Psm[(pr    ) * SK_S + kk * 8 + tig    ]);
            pa[1] = __float_as_uint(Psm[(pr + 8) * SK_S + kk * 8 + tig    ]);
            pa[2] = __float_as_uint(Psm[(pr    ) * SK_S + kk * 8 + tig + 4]);
            pa[3] = __float_as_uint(Psm[(pr + 8) * SK_S + kk * 8 + tig + 4]);
            #pragma unroll
            for (int n = 0; n < 8; n++) {
                uint32_t b0 = __float_as_uint(Vs[(kk * 8 + tig    ) * VS_S + n * 8 + gid]);
                uint32_t b1 = __float_as_uint(Vs[(kk * 8 + tig + 4) * VS_S + n * 8 + gid]);
                mma8(o[n], pa, b0, b1);
            }
        }
        // next iteration's top barrier protects K/V/P buffer reuse
    }

    // ---- normalize + write y[B,T,D], tf32-rounded for the proj GEMM ----
    const float i0 = 1.0f / l0;
    const float i1 = 1.0f / l1;
    float* yp = y + ((size_t)(b * SEQ + q0 + pr)) * DMODEL + h * HD;
    #pragma unroll
    for (int n = 0; n < 8; n++) {
        const int cc = n * 8 + 2 * tig;
        float2 w0, w1;
        w0.x = f2tf_f(o[n][0] * i0); w0.y = f2tf_f(o[n][1] * i0);
        w1.x = f2tf_f(o[n][2] * i1); w1.y = f2tf_f(o[n][3] * i1);
        *(float2*)&yp[cc]              = w0;
        *(float2*)&yp[8 * DMODEL + cc] = w1;
    }
}

// ---------------------------------------------------------------------------
// Launch
// ---------------------------------------------------------------------------
extern "C" void kernel_launch(void* const* d_in, const int* in_sizes, int n_in,
                              void* d_out, int out_size)
{
    const float* x     = (const float*)d_in[0];
    const float* Wqkv  = (const float*)d_in[1];
    const float* bqkv  = (const float*)d_in[2];
    const float* Wproj = (const float*)d_in[3];
    const float* bproj = (const float*)d_in[4];
    float* out = (float*)d_out;

    float *qkv = nullptr, *y = nullptr, *xr = nullptr, *wq = nullptr, *wp = nullptr;
    cudaGetSymbolAddress((void**)&qkv, g_qkv);
    cudaGetSymbolAddress((void**)&y,   g_y);
    cudaGetSymbolAddress((void**)&xr,  g_x);
    cudaGetSymbolAddress((void**)&wq,  g_wq);
    cudaGetSymbolAddress((void**)&wp,  g_wp);

    cudaFuncSetAttribute(gemm_tf32<true>,
                         cudaFuncAttributeMaxDynamicSharedMemorySize, GEMM_SMEM);
    cudaFuncSetAttribute(gemm_tf32<false>,
                         cudaFuncAttributeMaxDynamicSharedMemorySize, GEMM_SMEM);
    cudaFuncSetAttribute(attn_tf32,
                         cudaFuncAttributeMaxDynamicSharedMemorySize, ATTN_SMEM);

    // 0) Pre-round inputs/weights to the tf32 grid (makes HW truncation exact)
    {
        int n4;
        n4 = MTOT * DMODEL / 4;
        round_tf32<<<(n4 + 255) / 256, 256>>>(x, xr, n4);
        n4 = DMODEL * 3 * DMODEL / 4;
        round_tf32<<<(n4 + 255) / 256, 256>>>(Wqkv, wq, n4);
        n4 = DMODEL * DMODEL / 4;
        round_tf32<<<(n4 + 255) / 256, 256>>>(Wproj, wp, n4);
    }

    // 1) QKV projection: [8192,1024] @ [1024,3072] + b  -> tf32-rounded qkv
    gemm_tf32<true><<<dim3(3 * DMODEL / 128, MTOT / 128), 256, GEMM_SMEM>>>(
        MTOT, 3 * DMODEL, DMODEL, xr, wq, bqkv, qkv);

    // 2) Flash attention (tensor core) -> tf32-rounded y [B,T,D]
    attn_tf32<<<dim3(SEQ / 64, NHEAD, BATCH), 128, ATTN_SMEM>>>(qkv, y);

    // 3) Output projection: [8192,1024] @ [1024,1024] + b -> fp32 out
    gemm_tf32<false><<<dim3(DMODEL / 128, MTOT / 128), 256, GEMM_SMEM>>>(
        MTOT, DMODEL, DMODEL, y, wp, bproj, out);
}

// round 8
// speedup vs baseline: 5.5794x; 1.4788x over previous
#include <cuda_runtime.h>
#include <cuda_fp16.h>
#include <math.h>
#include <stdint.h>

// Problem constants
#define BATCH  4
#define SEQ    2048
#define DMODEL 1024
#define NHEAD  16
#define HD     64
#define MTOT   (BATCH * SEQ)   // 8192

// Scratch (allocation-free: __device__ globals) — fp16 activations/weights
__device__ __half g_qkv[(size_t)BATCH * SEQ * 3 * DMODEL];  // [B,T,3D]
__device__ __half g_y  [(size_t)BATCH * SEQ * DMODEL];      // [B,T,D]
__device__ __half g_x  [(size_t)MTOT * DMODEL];
__device__ __half g_wq [(size_t)DMODEL * 3 * DMODEL];
__device__ __half g_wp [(size_t)DMODEL * DMODEL];

// ---------------------------------------------------------------------------
// Helpers
// ---------------------------------------------------------------------------
__device__ __forceinline__ void mma16(float* c, const uint32_t* a,
                                      uint32_t b0, uint32_t b1) {
    asm volatile(
        "mma.sync.aligned.m16n8k16.row.col.f32.f16.f16.f32 "
        "{%0,%1,%2,%3},{%4,%5,%6,%7},{%8,%9},{%0,%1,%2,%3};\n"
        : "+f"(c[0]), "+f"(c[1]), "+f"(c[2]), "+f"(c[3])
        : "r"(a[0]), "r"(a[1]), "r"(a[2]), "r"(a[3]), "r"(b0), "r"(b1));
}
__device__ __forceinline__ void ldsm4(uint32_t& r0, uint32_t& r1,
                                      uint32_t& r2, uint32_t& r3, uint32_t a) {
    asm volatile("ldmatrix.sync.aligned.m8n8.x4.shared.b16 {%0,%1,%2,%3}, [%4];"
                 : "=r"(r0), "=r"(r1), "=r"(r2), "=r"(r3) : "r"(a));
}
__device__ __forceinline__ void ldsm4t(uint32_t& r0, uint32_t& r1,
                                       uint32_t& r2, uint32_t& r3, uint32_t a) {
    asm volatile("ldmatrix.sync.aligned.m8n8.x4.trans.shared.b16 {%0,%1,%2,%3}, [%4];"
                 : "=r"(r0), "=r"(r1), "=r"(r2), "=r"(r3) : "r"(a));
}
__device__ __forceinline__ void cp_async16(uint32_t smem_dst, const void* gsrc) {
    asm volatile("cp.async.cg.shared.global [%0], [%1], 16;\n"
                 :: "r"(smem_dst), "l"(gsrc));
}
__device__ __forceinline__ void cp_commit() {
    asm volatile("cp.async.commit_group;\n");
}
template <int N>
__device__ __forceinline__ void cp_wait() {
    asm volatile("cp.async.wait_group %0;\n" :: "n"(N));
}

// ---------------------------------------------------------------------------
// fp32 -> fp16 convert (one-shot)
// ---------------------------------------------------------------------------
__global__ void to_half(const float* __restrict__ in, __half* __restrict__ out,
                        int n4)
{
    int i = blockIdx.x * blockDim.x + threadIdx.x;
    if (i < n4) {
        float4 v = ((const float4*)in)[i];
        __half2* o = (__half2*)out + 2 * (size_t)i;
        o[0] = __floats2half2_rn(v.x, v.y);
        o[1] = __floats2half2_rn(v.z, v.w);
    }
}

// ---------------------------------------------------------------------------
// fp16 tensor-core GEMM + bias, cp.async 4-stage ring, ldmatrix fragments.
// C[M,N] = A[M,K] @ W[K,N] + bias.  BM=BN=128, BK=32, 8 warps (2x4),
// warp tile 64x32, m16n8k16.  A rows 40 halfs (80B), B rows 136 halfs (272B):
// both stride%128B = 16 -> conflict-free LDSM phases.
// ---------------------------------------------------------------------------
#define AS2 40
#define BS2 136
#define G_STAGES 4
#define A_STGH (128 * AS2)       // halfs per A stage (5120)
#define B_STGH (32 * BS2)        // halfs per B stage (4352)
#define GEMM_SMEM ((G_STAGES * (A_STGH + B_STGH)) * 2)   // 75776 B

template <bool HALF_OUT>
__global__ void __launch_bounds__(256, 1)
gemm_fp16(int M, int N, int K,
          const __half* __restrict__ A,
          const __half* __restrict__ W,
          const float* __restrict__ bias,
          void* __restrict__ Cv)
{
    extern __shared__ __half dsm[];
    __half* As = dsm;
    __half* Bs = dsm + G_STAGES * A_STGH;
    const uint32_t as_u32 = (uint32_t)__cvta_generic_to_shared(As);
    const uint32_t bs_u32 = (uint32_t)__cvta_generic_to_shared(Bs);

    const int tid  = threadIdx.x;
    const int wid  = tid >> 5;
    const int lane = tid & 31;
    const int gid  = lane >> 2;
    const int tig  = lane & 3;
    const int wm   = wid >> 2;   // 0..1
    const int wn   = wid & 3;    // 0..3

    const __half* Ab = A + (size_t)blockIdx.y * 128 * K;
    const __half* Wb = W + (size_t)blockIdx.x * 128;

    // cp.async maps
    const int aRow = tid >> 1;              // 0..127
    const int aC0  = (tid & 1) * 2;         // chunk 0..3 (16B each)
    const int bRow = tid >> 3;              // 0..31
    const int bC0  = (tid & 7) * 2;         // chunk 0..15

    // ldmatrix lane components
    const int j    = lane >> 3;             // matrix idx 0..3
    const int l7   = lane & 7;
    const int aLr  = (j & 1) * 8 + l7;      // A/P row-style
    const int aLc  = (j >> 1) * 8;
    const int bLk  = (j & 1) * 8 + l7;      // B trans k-row
    const int bLn  = (j >> 1) * 8;

    float c[4][4][4];
    #pragma unroll
    for (int i = 0; i < 4; i++)
        #pragma unroll
        for (int jj = 0; jj < 4; jj++)
            #pragma unroll
            for (int r = 0; r < 4; r++) c[i][jj][r] = 0.0f;

    const int T = K / 32;

    auto issue = [&](int kt, int s) {
        uint32_t ad = as_u32 + (uint32_t)(s * A_STGH + aRow * AS2) * 2;
        const __half* asrc = Ab + (size_t)aRow * K + kt * 32;
        #pragma unroll
        for (int i = 0; i < 2; i++)
            cp_async16(ad + (aC0 + i) * 16, asrc + (aC0 + i) * 8);
        uint32_t bd = bs_u32 + (uint32_t)(s * B_STGH + bRow * BS2) * 2;
        const __half* bsrc = Wb + (size_t)(kt * 32 + bRow) * N;
        #pragma unroll
        for (int i = 0; i < 2; i++)
            cp_async16(bd + (bC0 + i) * 16, bsrc + (bC0 + i) * 8);
        cp_commit();
    };

    issue(0, 0);
    issue(1, 1);
    issue(2, 2);

    for (int t = 0; t < T; t++) {
        cp_wait<2>();
        __syncthreads();
        if (t + 3 < T) issue(t + 3, (t + 3) & 3);

        const uint32_t abase = as_u32 + (uint32_t)((t & 3) * A_STGH) * 2;
        const uint32_t bbase = bs_u32 + (uint32_t)((t & 3) * B_STGH) * 2;

        #pragma unroll
        for (int kk = 0; kk < 32; kk += 16) {
            uint32_t a[4][4];
            #pragma unroll
            for (int mt = 0; mt < 4; mt++) {
                uint32_t ad = abase +
                    (uint32_t)((wm * 64 + mt * 16 + aLr) * AS2 + kk + aLc) * 2;
                ldsm4(a[mt][0], a[mt][1], a[mt][2], a[mt][3], ad);
            }
            uint32_t bg[2][4];
            #pragma unroll
            for (int g = 0; g < 2; g++) {
                uint32_t bd = bbase +
                    (uint32_t)((kk + bLk) * BS2 + wn * 32 + g * 16 + bLn) * 2;
                ldsm4t(bg[g][0], bg[g][1], bg[g][2], bg[g][3], bd);
            }
            #pragma unroll
            for (int mt = 0; mt < 4; mt++)
                #pragma unroll
                for (int g = 0; g < 2; g++) {
                    mma16(c[mt][2 * g],     a[mt], bg[g][0], bg[g][1]);
                    mma16(c[mt][2 * g + 1], a[mt], bg[g][2], bg[g][3]);
                }
        }
    }

    // Epilogue
    #pragma unroll
    for (int mt = 0; mt < 4; mt++) {
        const int r = blockIdx.y * 128 + wm * 64 + mt * 16 + gid;
        #pragma unroll
        for (int nt = 0; nt < 4; nt++) {
            const int col = blockIdx.x * 128 + wn * 32 + nt * 8 + 2 * tig;
            float2 bv = *(const float2*)&bias[col];
            if (HALF_OUT) {
                __half* C = (__half*)Cv;
                *(__half2*)&C[(size_t)(r    ) * N + col] =
                    __floats2half2_rn(c[mt][nt][0] + bv.x, c[mt][nt][1] + bv.y);
                *(__half2*)&C[(size_t)(r + 8) * N + col] =
                    __floats2half2_rn(c[mt][nt][2] + bv.x, c[mt][nt][3] + bv.y);
            } else {
                float* C = (float*)Cv;
                float2 o0, o1;
                o0.x = c[mt][nt][0] + bv.x; o0.y = c[mt][nt][1] + bv.y;
                o1.x = c[mt][nt][2] + bv.x; o1.y = c[mt][nt][3] + bv.y;
                *(float2*)&C[(size_t)(r    ) * N + col] = o0;
                *(float2*)&C[(size_t)(r + 8) * N + col] = o1;
            }
        }
    }
}

// ---------------------------------------------------------------------------
// fp16 tensor-core flash attention. Br=64 (4 warps x 16 rows), Bc=64,
// m16n8k16, ldmatrix frags, cp.async double-buffered K/V, static 46KB smem.
// K used non-trans ([key][hd] == B's n-k layout), V via ldmatrix.trans,
// P/Q buffer shared (warp-private rows). Softmax scale folded post-MMA.
// ---------------------------------------------------------------------------
#define AT_S 72   // halfs per row (144B; %128B == 16 -> conflict-free)

__global__ void __launch_bounds__(128, 2)
attn_fp16(const __half* __restrict__ qkv, __half* __restrict__ y)
{
    __shared__ __half Ksm[2][64 * AT_S];
    __shared__ __half Vsm[2][64 * AT_S];
    __shared__ __half Pq [64 * AT_S];
    const uint32_t k_u32 = (uint32_t)__cvta_generic_to_shared(Ksm);
    const uint32_t v_u32 = (uint32_t)__cvta_generic_to_shared(Vsm);
    const uint32_t p_u32 = (uint32_t)__cvta_generic_to_shared(Pq);

    const int b    = blockIdx.z;
    const int h    = blockIdx.y;
    const int q0   = blockIdx.x * 64;
    const int tid  = threadIdx.x;
    const int wid  = tid >> 5;
    const int lane = tid & 31;
    const int gid  = lane >> 2;
    const int tig  = lane & 3;
    const int pr   = wid * 16 + gid;

    // cp.async map: row = tid/2 (0..63), 4 of 8 chunks per thread
    const int sRow = tid >> 1;
    const int sC0  = (tid & 1) * 4;

    // ldmatrix lane components
    const int j   = lane >> 3;
    const int l7  = lane & 7;
    const int aLr = (j & 1) * 8 + l7;   // A-style (Q/P) row
    const int aLc = (j >> 1) * 8;
    const int nLr = (j >> 1) * 8 + l7;  // K non-trans n-row
    const int nLc = (j & 1) * 8;
    const int vLk = (j & 1) * 8 + l7;   // V trans key-row
    const int vLn = (j >> 1) * 8;

    auto issue_q = [&]() {
        const __half* src = qkv + ((size_t)(b * SEQ + q0 + sRow)) * (3 * DMODEL)
                          + h * HD;
        uint32_t qd = p_u32 + (uint32_t)(sRow * AT_S) * 2;
        #pragma unroll
        for (int i = 0; i < 4; i++)
            cp_async16(qd + (sC0 + i) * 16, src + (sC0 + i) * 8);
        cp_commit();
    };
    auto issue_kv = [&](int kt, int s) {
        const __half* src = qkv + ((size_t)(b * SEQ + kt + sRow)) * (3 * DMODEL)
                          + DMODEL + h * HD;
        uint32_t kd = k_u32 + (uint32_t)(s * 64 * AT_S + sRow * AT_S) * 2;
        uint32_t vd = v_u32 + (uint32_t)(s * 64 * AT_S + sRow * AT_S) * 2;
        #pragma unroll
        for (int i = 0; i < 4; i++) {
            cp_async16(kd + (sC0 + i) * 16, src + (sC0 + i) * 8);
            cp_async16(vd + (sC0 + i) * 16, src + DMODEL + (sC0 + i) * 8);
        }
        cp_commit();
    };

    issue_q();
    issue_kv(0, 0);
    cp_wait<0>();
    __syncthreads();

    // Q fragments resident (4 k16 slabs)
    uint32_t qa[4][4];
    #pragma unroll
    for (int s = 0; s < 4; s++) {
        uint32_t ad = p_u32 + (uint32_t)((wid * 16 + aLr) * AT_S + s * 16 + aLc) * 2;
        ldsm4(qa[s][0], qa[s][1], qa[s][2], qa[s][3], ad);
    }

    float o[8][4];
    #pragma unroll
    for (int n = 0; n < 8; n++)
        #pragma unroll
        for (int q = 0; q < 4; q++) o[n][q] = 0.0f;
    float m0 = -1e30f, m1 = -1e30f, l0 = 0.0f, l1 = 0.0f;

    const int NT = SEQ / 64;
    for (int t = 0; t < NT; t++) {
        if (t > 0) {
            cp_wait<0>();
            __syncthreads();
        }
        if (t + 1 < NT) issue_kv((t + 1) * 64, (t + 1) & 1);

        const uint32_t kb = k_u32 + (uint32_t)((t & 1) * 64 * AT_S) * 2;
        const uint32_t vb = v_u32 + (uint32_t)((t & 1) * 64 * AT_S) * 2;

        // ---- S = Q K^T (fp32 frags) ----
        float s[8][4];
        #pragma unroll
        for (int n = 0; n < 8; n++)
            #pragma unroll
            for (int q = 0; q < 4; q++) s[n][q] = 0.0f;
        #pragma unroll
        for (int sl = 0; sl < 4; sl++) {
            const int kk = sl * 16;
            #pragma unroll
            for (int g = 0; g < 4; g++) {
                uint32_t r0, r1, r2, r3;
                uint32_t kd = kb + (uint32_t)((g * 16 + nLr) * AT_S + kk + nLc) * 2;
                ldsm4(r0, r1, r2, r3, kd);
                mma16(s[2 * g],     qa[sl], r0, r1);
                mma16(s[2 * g + 1], qa[sl], r2, r3);
            }
        }
        #pragma unroll
        for (int n = 0; n < 8; n++) {
            s[n][0] *= 0.125f; s[n][1] *= 0.125f;
            s[n][2] *= 0.125f; s[n][3] *= 0.125f;
        }

        // ---- online softmax (rows pr, pr+8) ----
        float mx0 = -1e30f, mx1 = -1e30f;
        #pragma unroll
        for (int n = 0; n < 8; n++) {
            mx0 = fmaxf(mx0, fmaxf(s[n][0], s[n][1]));
            mx1 = fmaxf(mx1, fmaxf(s[n][2], s[n][3]));
        }
        mx0 = fmaxf(mx0, __shfl_xor_sync(0xffffffffu, mx0, 1));
        mx0 = fmaxf(mx0, __shfl_xor_sync(0xffffffffu, mx0, 2));
        mx1 = fmaxf(mx1, __shfl_xor_sync(0xffffffffu, mx1, 1));
        mx1 = fmaxf(mx1, __shfl_xor_sync(0xffffffffu, mx1, 2));
        const float mn0 = fmaxf(m0, mx0);
        const float mn1 = fmaxf(m1, mx1);
        const float al0 = __expf(m0 - mn0);
        const float al1 = __expf(m1 - mn1);
        m0 = mn0; m1 = mn1;

        float sum0 = 0.0f, sum1 = 0.0f;
        #pragma unroll
        for (int n = 0; n < 8; n++) {
            s[n][0] = __expf(s[n][0] - mn0); sum0 += s[n][0];
            s[n][1] = __expf(s[n][1] - mn0); sum0 += s[n][1];
            s[n][2] = __expf(s[n][2] - mn1); sum1 += s[n][2];
            s[n][3] = __expf(s[n][3] - mn1); sum1 += s[n][3];
        }
        sum0 += __shfl_xor_sync(0xffffffffu, sum0, 1);
        sum0 += __shfl_xor_sync(0xffffffffu, sum0, 2);
        sum1 += __shfl_xor_sync(0xffffffffu, sum1, 1);
        sum1 += __shfl_xor_sync(0xffffffffu, sum1, 2);
        l0 = l0 * al0 + sum0;
        l1 = l1 * al1 + sum1;

        #pragma unroll
        for (int n = 0; n < 8; n++) {
            o[n][0] *= al0; o[n][1] *= al0;
            o[n][2] *= al1; o[n][3] *= al1;
        }

        // ---- P -> smem (fp16), warp-private rows ----
        #pragma unroll
        for (int n = 0; n < 8; n++) {
            *(__half2*)&Pq[(pr    ) * AT_S + n * 8 + 2 * tig] =
                __floats2half2_rn(s[n][0], s[n][1]);
            *(__half2*)&Pq[(pr + 8) * AT_S + n * 8 + 2 * tig] =
                __floats2half2_rn(s[n][2], s[n][3]);
        }
        __syncwarp();

        // ---- O += P @ V ----
        #pragma unroll
        for (int sl = 0; sl < 4; sl++) {
            const int kk = sl * 16;
            uint32_t pa[4];
            {
                uint32_t pd = p_u32 +
                    (uint32_t)((wid * 16 + aLr) * AT_S + kk + aLc) * 2;
                ldsm4(pa[0], pa[1], pa[2], pa[3], pd);
            }
            #pragma unroll
            for (int g = 0; g < 4; g++) {
                uint32_t r0, r1, r2, r3;
                uint32_t vd = vb + (uint32_t)((kk + vLk) * AT_S + g * 16 + vLn) * 2;
                ldsm4t(r0, r1, r2, r3, vd);
                mma16(o[2 * g],     pa, r0, r1);
                mma16(o[2 * g + 1], pa, r2, r3);
            }
        }
    }

    // ---- normalize + write y (fp16) ----
    const float i0 = 1.0f / l0;
    const float i1 = 1.0f / l1;
    __half* yp = y + ((size_t)(b * SEQ + q0 + pr)) * DMODEL + h * HD;
    #pragma unroll
    for (int n = 0; n < 8; n++) {
        const int cc = n * 8 + 2 * tig;
        *(__half2*)&yp[cc] = __floats2half2_rn(o[n][0] * i0, o[n][1] * i0);
        *(__half2*)&yp[8 * DMODEL + cc] =
            __floats2half2_rn(o[n][2] * i1, o[n][3] * i1);
    }
}

// ---------------------------------------------------------------------------
// Launch
// ---------------------------------------------------------------------------
extern "C" void kernel_launch(void* const* d_in, const int* in_sizes, int n_in,
                              void* d_out, int out_size)
{
    const float* x     = (const float*)d_in[0];
    const float* Wqkv  = (const float*)d_in[1];
    const float* bqkv  = (const float*)d_in[2];
    const float* Wproj = (const float*)d_in[3];
    const float* bproj = (const float*)d_in[4];
    float* out = (float*)d_out;

    __half *qkv = nullptr, *y = nullptr, *xh = nullptr, *wq = nullptr, *wp = nullptr;
    cudaGetSymbolAddress((void**)&qkv, g_qkv);
    cudaGetSymbolAddress((void**)&y,   g_y);
    cudaGetSymbolAddress((void**)&xh,  g_x);
    cudaGetSymbolAddress((void**)&wq,  g_wq);
    cudaGetSymbolAddress((void**)&wp,  g_wp);

    cudaFuncSetAttribute(gemm_fp16<true>,
                         cudaFuncAttributeMaxDynamicSharedMemorySize, GEMM_SMEM);
    cudaFuncSetAttribute(gemm_fp16<false>,
                         cudaFuncAttributeMaxDynamicSharedMemorySize, GEMM_SMEM);

    // 0) convert inputs/weights to fp16
    {
        int n4;
        n4 = MTOT * DMODEL / 4;
        to_half<<<(n4 + 255) / 256, 256>>>(x, xh, n4);
        n4 = DMODEL * 3 * DMODEL / 4;
        to_half<<<(n4 + 255) / 256, 256>>>(Wqkv, wq, n4);
        n4 = DMODEL * DMODEL / 4;
        to_half<<<(n4 + 255) / 256, 256>>>(Wproj, wp, n4);
    }

    // 1) QKV projection -> fp16 qkv
    gemm_fp16<true><<<dim3(3 * DMODEL / 128, MTOT / 128), 256, GEMM_SMEM>>>(
        MTOT, 3 * DMODEL, DMODEL, xh, wq, bqkv, qkv);

    // 2) flash attention -> fp16 y
    attn_fp16<<<dim3(SEQ / 64, NHEAD, BATCH), 128>>>(qkv, y);

    // 3) output projection -> fp32 out
    gemm_fp16<false><<<dim3(DMODEL / 128, MTOT / 128), 256, GEMM_SMEM>>>(
        MTOT, DMODEL, DMODEL, y, wp, bproj, out);
}

// round 11
// speedup vs baseline: 6.3454x; 1.1373x over previous
#include <cuda_runtime.h>
#include <cuda_fp16.h>
#include <math.h>
#include <stdint.h>

// Problem constants
#define BATCH  4
#define SEQ    2048
#define DMODEL 1024
#define NHEAD  16
#define HD     64
#define MTOT   (BATCH * SEQ)   // 8192

// Scratch (allocation-free: __device__ globals) — fp16 activations/weights
__device__ __half g_qkv[(size_t)BATCH * SEQ * 3 * DMODEL];  // [B,T,3D]
__device__ __half g_y  [(size_t)BATCH * SEQ * DMODEL];      // [B,T,D]
__device__ __half g_x  [(size_t)MTOT * DMODEL];
__device__ __half g_wq [(size_t)DMODEL * 3 * DMODEL];
__device__ __half g_wp [(size_t)DMODEL * DMODEL];

// ---------------------------------------------------------------------------
// Helpers
// ---------------------------------------------------------------------------
__device__ __forceinline__ void mma16(float* c, const uint32_t* a,
                                      uint32_t b0, uint32_t b1) {
    asm volatile(
        "mma.sync.aligned.m16n8k16.row.col.f32.f16.f16.f32 "
        "{%0,%1,%2,%3},{%4,%5,%6,%7},{%8,%9},{%0,%1,%2,%3};\n"
        : "+f"(c[0]), "+f"(c[1]), "+f"(c[2]), "+f"(c[3])
        : "r"(a[0]), "r"(a[1]), "r"(a[2]), "r"(a[3]), "r"(b0), "r"(b1));
}
__device__ __forceinline__ void ldsm4(uint32_t& r0, uint32_t& r1,
                                      uint32_t& r2, uint32_t& r3, uint32_t a) {
    asm volatile("ldmatrix.sync.aligned.m8n8.x4.shared.b16 {%0,%1,%2,%3}, [%4];"
                 : "=r"(r0), "=r"(r1), "=r"(r2), "=r"(r3) : "r"(a));
}
__device__ __forceinline__ void ldsm4t(uint32_t& r0, uint32_t& r1,
                                       uint32_t& r2, uint32_t& r3, uint32_t a) {
    asm volatile("ldmatrix.sync.aligned.m8n8.x4.trans.shared.b16 {%0,%1,%2,%3}, [%4];"
                 : "=r"(r0), "=r"(r1), "=r"(r2), "=r"(r3) : "r"(a));
}
__device__ __forceinline__ void cp_async16(uint32_t smem_dst, const void* gsrc) {
    asm volatile("cp.async.cg.shared.global [%0], [%1], 16;\n"
                 :: "r"(smem_dst), "l"(gsrc));
}
__device__ __forceinline__ void cp_commit() {
    asm volatile("cp.async.commit_group;\n");
}
template <int N>
__device__ __forceinline__ void cp_wait() {
    asm volatile("cp.async.wait_group %0;\n" :: "n"(N));
}
__device__ __forceinline__ float fast_ex2(float x) {
    float r;
    asm("ex2.approx.f32 %0, %1;" : "=f"(r) : "f"(x));
    return r;
}

// ---------------------------------------------------------------------------
// fp32 -> fp16 convert (one-shot)
// ---------------------------------------------------------------------------
__global__ void to_half(const float* __restrict__ in, __half* __restrict__ out,
                        int n4)
{
    int i = blockIdx.x * blockDim.x + threadIdx.x;
    if (i < n4) {
        float4 v = ((const float4*)in)[i];
        __half2* o = (__half2*)out + 2 * (size_t)i;
        o[0] = __floats2half2_rn(v.x, v.y);
        o[1] = __floats2half2_rn(v.z, v.w);
    }
}

// ---------------------------------------------------------------------------
// fp16 tensor-core GEMM + bias, cp.async 3-stage ring, ldmatrix fragments,
// 2 CTAs/SM (launch_bounds(256,2); 57KB smem/CTA).
// C[M,N] = A[M,K] @ W[K,N] + bias.  BM=BN=128, BK=32, 8 warps (2x4),
// warp tile 64x32, m16n8k16.  A rows 40 halfs (80B), B rows 136 halfs (272B):
// both stride%128B = 16 -> conflict-free LDSM phases.
// ---------------------------------------------------------------------------
#define AS2 40
#define BS2 136
#define G_STAGES 3
#define A_STGH (128 * AS2)       // halfs per A stage (5120)
#define B_STGH (32 * BS2)        // halfs per B stage (4352)
#define GEMM_SMEM ((G_STAGES * (A_STGH + B_STGH)) * 2)   // 56832 B

template <bool HALF_OUT>
__global__ void __launch_bounds__(256, 2)
gemm_fp16(int M, int N, int K,
          const __half* __restrict__ A,
          const __half* __restrict__ W,
          const float* __restrict__ bias,
          void* __restrict__ Cv)
{
    extern __shared__ __half dsm[];
    __half* As = dsm;
    __half* Bs = dsm + G_STAGES * A_STGH;
    const uint32_t as_u32 = (uint32_t)__cvta_generic_to_shared(As);
    const uint32_t bs_u32 = (uint32_t)__cvta_generic_to_shared(Bs);

    const int tid  = threadIdx.x;
    const int wid  = tid >> 5;
    const int lane = tid & 31;
    const int gid  = lane >> 2;
    const int tig  = lane & 3;
    const int wm   = wid >> 2;   // 0..1
    const int wn   = wid & 3;    // 0..3

    const __half* Ab = A + (size_t)blockIdx.y * 128 * K;
    const __half* Wb = W + (size_t)blockIdx.x * 128;

    // cp.async maps
    const int aRow = tid >> 1;              // 0..127
    const int aC0  = (tid & 1) * 2;         // chunk 0..3 (16B each)
    const int bRow = tid >> 3;              // 0..31
    const int bC0  = (tid & 7) * 2;         // chunk 0..15

    // ldmatrix lane components
    const int j    = lane >> 3;             // matrix idx 0..3
    const int l7   = lane & 7;
    const int aLr  = (j & 1) * 8 + l7;      // A row-style
    const int aLc  = (j >> 1) * 8;
    const int bLk  = (j & 1) * 8 + l7;      // B trans k-row
    const int bLn  = (j >> 1) * 8;

    float c[4][4][4];
    #pragma unroll
    for (int i = 0; i < 4; i++)
        #pragma unroll
        for (int jj = 0; jj < 4; jj++)
            #pragma unroll
            for (int r = 0; r < 4; r++) c[i][jj][r] = 0.0f;

    const int T = K / 32;

    auto issue = [&](int kt, int s) {
        uint32_t ad = as_u32 + (uint32_t)(s * A_STGH + aRow * AS2) * 2;
        const __half* asrc = Ab + (size_t)aRow * K + kt * 32;
        #pragma unroll
        for (int i = 0; i < 2; i++)
            cp_async16(ad + (aC0 + i) * 16, asrc + (aC0 + i) * 8);
        uint32_t bd = bs_u32 + (uint32_t)(s * B_STGH + bRow * BS2) * 2;
        const __half* bsrc = Wb + (size_t)(kt * 32 + bRow) * N;
        #pragma unroll
        for (int i = 0; i < 2; i++)
            cp_async16(bd + (bC0 + i) * 16, bsrc + (bC0 + i) * 8);
        cp_commit();
    };

    issue(0, 0);
    issue(1, 1);

    for (int t = 0; t < T; t++) {
        if (t == T - 1) cp_wait<0>(); else cp_wait<1>();
        __syncthreads();
        if (t + 2 < T) issue(t + 2, (t + 2) % G_STAGES);

        const uint32_t abase = as_u32 + (uint32_t)((t % G_STAGES) * A_STGH) * 2;
        const uint32_t bbase = bs_u32 + (uint32_t)((t % G_STAGES) * B_STGH) * 2;

        #pragma unroll
        for (int kk = 0; kk < 32; kk += 16) {
            uint32_t a[4][4];
            #pragma unroll
            for (int mt = 0; mt < 4; mt++) {
                uint32_t ad = abase +
                    (uint32_t)((wm * 64 + mt * 16 + aLr) * AS2 + kk + aLc) * 2;
                ldsm4(a[mt][0], a[mt][1], a[mt][2], a[mt][3], ad);
            }
            uint32_t bg[2][4];
            #pragma unroll
            for (int g = 0; g < 2; g++) {
                uint32_t bd = bbase +
                    (uint32_t)((kk + bLk) * BS2 + wn * 32 + g * 16 + bLn) * 2;
                ldsm4t(bg[g][0], bg[g][1], bg[g][2], bg[g][3], bd);
            }
            #pragma unroll
            for (int mt = 0; mt < 4; mt++)
                #pragma unroll
                for (int g = 0; g < 2; g++) {
                    mma16(c[mt][2 * g],     a[mt], bg[g][0], bg[g][1]);
                    mma16(c[mt][2 * g + 1], a[mt], bg[g][2], bg[g][3]);
                }
        }
        __syncthreads();
    }

    // Epilogue
    #pragma unroll
    for (int mt = 0; mt < 4; mt++) {
        const int r = blockIdx.y * 128 + wm * 64 + mt * 16 + gid;
        #pragma unroll
        for (int nt = 0; nt < 4; nt++) {
            const int col = blockIdx.x * 128 + wn * 32 + nt * 8 + 2 * tig;
            float2 bv = *(const float2*)&bias[col];
            if (HALF_OUT) {
                __half* C = (__half*)Cv;
                *(__half2*)&C[(size_t)(r    ) * N + col] =
                    __floats2half2_rn(c[mt][nt][0] + bv.x, c[mt][nt][1] + bv.y);
                *(__half2*)&C[(size_t)(r + 8) * N + col] =
                    __floats2half2_rn(c[mt][nt][2] + bv.x, c[mt][nt][3] + bv.y);
            } else {
                float* C = (float*)Cv;
                float2 o0, o1;
                o0.x = c[mt][nt][0] + bv.x; o0.y = c[mt][nt][1] + bv.y;
                o1.x = c[mt][nt][2] + bv.x; o1.y = c[mt][nt][3] + bv.y;
                *(float2*)&C[(size_t)(r    ) * N + col] = o0;
                *(float2*)&C[(size_t)(r + 8) * N + col] = o1;
            }
        }
    }
}

// ---------------------------------------------------------------------------
// fp16 tensor-core flash attention. Br=64 (4 warps x 16 rows), Bc=64,
// m16n8k16, ldmatrix frags, cp.async double-buffered K/V, 46KB static smem,
// 3 CTAs/SM. Softmax in base-2: scale*log2(e) folded post-MMA, ex2.approx.
// ---------------------------------------------------------------------------
#define AT_S 72   // halfs per row (144B; %128B == 16 -> conflict-free)
#define SCALE_LOG2E 0.1803368801111244f   // 0.125 * log2(e)

__global__ void __launch_bounds__(128, 3)
attn_fp16(const __half* __restrict__ qkv, __half* __restrict__ y)
{
    __shared__ __half Ksm[2][64 * AT_S];
    __shared__ __half Vsm[2][64 * AT_S];
    __shared__ __half Pq [64 * AT_S];
    const uint32_t k_u32 = (uint32_t)__cvta_generic_to_shared(Ksm);
    const uint32_t v_u32 = (uint32_t)__cvta_generic_to_shared(Vsm);
    const uint32_t p_u32 = (uint32_t)__cvta_generic_to_shared(Pq);

    const int b    = blockIdx.z;
    const int h    = blockIdx.y;
    const int q0   = blockIdx.x * 64;
    const int tid  = threadIdx.x;
    const int wid  = tid >> 5;
    const int lane = tid & 31;
    const int gid  = lane >> 2;
    const int tig  = lane & 3;
    const int pr   = wid * 16 + gid;

    const int sRow = tid >> 1;
    const int sC0  = (tid & 1) * 4;

    const int j   = lane >> 3;
    const int l7  = lane & 7;
    const int aLr = (j & 1) * 8 + l7;
    const int aLc = (j >> 1) * 8;
    const int nLr = (j >> 1) * 8 + l7;
    const int nLc = (j & 1) * 8;
    const int vLk = (j & 1) * 8 + l7;
    const int vLn = (j >> 1) * 8;

    auto issue_q = [&]() {
        const __half* src = qkv + ((size_t)(b * SEQ + q0 + sRow)) * (3 * DMODEL)
                          + h * HD;
        uint32_t qd = p_u32 + (uint32_t)(sRow * AT_S) * 2;
        #pragma unroll
        for (int i = 0; i < 4; i++)
            cp_async16(qd + (sC0 + i) * 16, src + (sC0 + i) * 8);
        cp_commit();
    };
    auto issue_kv = [&](int kt, int s) {
        const __half* src = qkv + ((size_t)(b * SEQ + kt + sRow)) * (3 * DMODEL)
                          + DMODEL + h * HD;
        uint32_t kd = k_u32 + (uint32_t)(s * 64 * AT_S + sRow * AT_S) * 2;
        uint32_t vd = v_u32 + (uint32_t)(s * 64 * AT_S + sRow * AT_S) * 2;
        #pragma unroll
        for (int i = 0; i < 4; i++) {
            cp_async16(kd + (sC0 + i) * 16, src + (sC0 + i) * 8);
            cp_async16(vd + (sC0 + i) * 16, src + DMODEL + (sC0 + i) * 8);
        }
        cp_commit();
    };

    issue_q();
    issue_kv(0, 0);
    cp_wait<0>();
    __syncthreads();

    uint32_t qa[4][4];
    #pragma unroll
    for (int s = 0; s < 4; s++) {
        uint32_t ad = p_u32 + (uint32_t)((wid * 16 + aLr) * AT_S + s * 16 + aLc) * 2;
        ldsm4(qa[s][0], qa[s][1], qa[s][2], qa[s][3], ad);
    }

    float o[8][4];
    #pragma unroll
    for (int n = 0; n < 8; n++)
        #pragma unroll
        for (int q = 0; q < 4; q++) o[n][q] = 0.0f;
    float m0 = -1e30f, m1 = -1e30f, l0 = 0.0f, l1 = 0.0f;

    const int NT = SEQ / 64;
    for (int t = 0; t < NT; t++) {
        if (t > 0) {
            cp_wait<0>();
            __syncthreads();
        }
        if (t + 1 < NT) issue_kv((t + 1) * 64, (t + 1) & 1);

        const uint32_t kb = k_u32 + (uint32_t)((t & 1) * 64 * AT_S) * 2;
        const uint32_t vb = v_u32 + (uint32_t)((t & 1) * 64 * AT_S) * 2;

        // ---- S = Q K^T, scaled into log2 domain ----
        float s[8][4];
        #pragma unroll
        for (int n = 0; n < 8; n++)
            #pragma unroll
            for (int q = 0; q < 4; q++) s[n][q] = 0.0f;
        #pragma unroll
        for (int sl = 0; sl < 4; sl++) {
            const int kk = sl * 16;
            #pragma unroll
            for (int g = 0; g < 4; g++) {
                uint32_t r0, r1, r2, r3;
                uint32_t kd = kb + (uint32_t)((g * 16 + nLr) * AT_S + kk + nLc) * 2;
                ldsm4(r0, r1, r2, r3, kd);
                mma16(s[2 * g],     qa[sl], r0, r1);
                mma16(s[2 * g + 1], qa[sl], r2, r3);
            }
        }
        #pragma unroll
        for (int n = 0; n < 8; n++) {
            s[n][0] *= SCALE_LOG2E; s[n][1] *= SCALE_LOG2E;
            s[n][2] *= SCALE_LOG2E; s[n][3] *= SCALE_LOG2E;
        }

        // ---- online softmax (base-2), rows pr and pr+8 ----
        float mx0 = -1e30f, mx1 = -1e30f;
        #pragma unroll
        for (int n = 0; n < 8; n++) {
            mx0 = fmaxf(mx0, fmaxf(s[n][0], s[n][1]));
            mx1 = fmaxf(mx1, fmaxf(s[n][2], s[n][3]));
        }
        mx0 = fmaxf(mx0, __shfl_xor_sync(0xffffffffu, mx0, 1));
        mx0 = fmaxf(mx0, __shfl_xor_sync(0xffffffffu, mx0, 2));
        mx1 = fmaxf(mx1, __shfl_xor_sync(0xffffffffu, mx1, 1));
        mx1 = fmaxf(mx1, __shfl_xor_sync(0xffffffffu, mx1, 2));
        const float mn0 = fmaxf(m0, mx0);
        const float mn1 = fmaxf(m1, mx1);
        const float al0 = fast_ex2(m0 - mn0);
        const float al1 = fast_ex2(m1 - mn1);
        m0 = mn0; m1 = mn1;

        float sum0 = 0.0f, sum1 = 0.0f;
        #pragma unroll
        for (int n = 0; n < 8; n++) {
            s[n][0] = fast_ex2(s[n][0] - mn0); sum0 += s[n][0];
            s[n][1] = fast_ex2(s[n][1] - mn0); sum0 += s[n][1];
            s[n][2] = fast_ex2(s[n][2] - mn1); sum1 += s[n][2];
            s[n][3] = fast_ex2(s[n][3] - mn1); sum1 += s[n][3];
        }
        sum0 += __shfl_xor_sync(0xffffffffu, sum0, 1);
        sum0 += __shfl_xor_sync(0xffffffffu, sum0, 2);
        sum1 += __shfl_xor_sync(0xffffffffu, sum1, 1);
        sum1 += __shfl_xor_sync(0xffffffffu, sum1, 2);
        l0 = l0 * al0 + sum0;
        l1 = l1 * al1 + sum1;

        #pragma unroll
        for (int n = 0; n < 8; n++) {
            o[n][0] *= al0; o[n][1] *= al0;
            o[n][2] *= al1; o[n][3] *= al1;
        }

        // ---- P -> smem (fp16), warp-private rows ----
        #pragma unroll
        for (int n = 0; n < 8; n++) {
            *(__half2*)&Pq[(pr    ) * AT_S + n * 8 + 2 * tig] =
                __floats2half2_rn(s[n][0], s[n][1]);
            *(__half2*)&Pq[(pr + 8) * AT_S + n * 8 + 2 * tig] =
                __floats2half2_rn(s[n][2], s[n][3]);
        }
        __syncwarp();

        // ---- O += P @ V ----
        #pragma unroll
        for (int sl = 0; sl < 4; sl++) {
            const int kk = sl * 16;
            uint32_t pa[4];
            {
                uint32_t pd = p_u32 +
                    (uint32_t)((wid * 16 + aLr) * AT_S + kk + aLc) * 2;
                ldsm4(pa[0], pa[1], pa[2], pa[3], pd);
            }
            #pragma unroll
            for (int g = 0; g < 4; g++) {
                uint32_t r0, r1, r2, r3;
                uint32_t vd = vb + (uint32_t)((kk + vLk) * AT_S + g * 16 + vLn) * 2;
                ldsm4t(r0, r1, r2, r3, vd);
                mma16(o[2 * g],     pa, r0, r1);
                mma16(o[2 * g + 1], pa, r2, r3);
            }
        }
    }

    const float i0 = 1.0f / l0;
    const float i1 = 1.0f / l1;
    __half* yp = y + ((size_t)(b * SEQ + q0 + pr)) * DMODEL + h * HD;
    #pragma unroll
    for (int n = 0; n < 8; n++) {
        const int cc = n * 8 + 2 * tig;
        *(__half2*)&yp[cc] = __floats2half2_rn(o[n][0] * i0, o[n][1] * i0);
        *(__half2*)&yp[8 * DMODEL + cc] =
            __floats2half2_rn(o[n][2] * i1, o[n][3] * i1);
    }
}

// ---------------------------------------------------------------------------
// Launch
// ---------------------------------------------------------------------------
extern "C" void kernel_launch(void* const* d_in, const int* in_sizes, int n_in,
                              void* d_out, int out_size)
{
    const float* x     = (const float*)d_in[0];
    const float* Wqkv  = (const float*)d_in[1];
    const float* bqkv  = (const float*)d_in[2];
    const float* Wproj = (const float*)d_in[3];
    const float* bproj = (const float*)d_in[4];
    float* out = (float*)d_out;

    __half *qkv = nullptr, *y = nullptr, *xh = nullptr, *wq = nullptr, *wp = nullptr;
    cudaGetSymbolAddress((void**)&qkv, g_qkv);
    cudaGetSymbolAddress((void**)&y,   g_y);
    cudaGetSymbolAddress((void**)&xh,  g_x);
    cudaGetSymbolAddress((void**)&wq,  g_wq);
    cudaGetSymbolAddress((void**)&wp,  g_wp);

    cudaFuncSetAttribute(gemm_fp16<true>,
                         cudaFuncAttributeMaxDynamicSharedMemorySize, GEMM_SMEM);
    cudaFuncSetAttribute(gemm_fp16<false>,
                         cudaFuncAttributeMaxDynamicSharedMemorySize, GEMM_SMEM);

    // 0) convert inputs/weights to fp16
    {
        int n4;
        n4 = MTOT * DMODEL / 4;
        to_half<<<(n4 + 255) / 256, 256>>>(x, xh, n4);
        n4 = DMODEL * 3 * DMODEL / 4;
        to_half<<<(n4 + 255) / 256, 256>>>(Wqkv, wq, n4);
        n4 = DMODEL * DMODEL / 4;
        to_half<<<(n4 + 255) / 256, 256>>>(Wproj, wp, n4);
    }

    // 1) QKV projection -> fp16 qkv
    gemm_fp16<true><<<dim3(3 * DMODEL / 128, MTOT / 128), 256, GEMM_SMEM>>>(
        MTOT, 3 * DMODEL, DMODEL, xh, wq, bqkv, qkv);

    // 2) flash attention -> fp16 y
    attn_fp16<<<dim3(SEQ / 64, NHEAD, BATCH), 128>>>(qkv, y);

    // 3) output projection -> fp32 out
    gemm_fp16<false><<<dim3(DMODEL / 128, MTOT / 128), 256, GEMM_SMEM>>>(
        MTOT, DMODEL, DMODEL, y, wp, bproj, out);
}

// round 12
// speedup vs baseline: 6.5721x; 1.0357x over previous
#include <cuda_runtime.h>
#include <cuda_fp16.h>
#include <math.h>
#include <stdint.h>

// Problem constants
#define BATCH  4
#define SEQ    2048
#define DMODEL 1024
#define NHEAD  16
#define HD     64
#define MTOT   (BATCH * SEQ)   // 8192

// Scratch (allocation-free: __device__ globals) — fp16 activations/weights
__device__ __half g_qkv[(size_t)BATCH * SEQ * 3 * DMODEL];  // [B,T,3D]
__device__ __half g_y  [(size_t)BATCH * SEQ * DMODEL];      // [B,T,D]
__device__ __half g_x  [(size_t)MTOT * DMODEL];
__device__ __half g_wq [(size_t)DMODEL * 3 * DMODEL];
__device__ __half g_wp [(size_t)DMODEL * DMODEL];

// ---------------------------------------------------------------------------
// Helpers
// ---------------------------------------------------------------------------
__device__ __forceinline__ void mma16(float* c, const uint32_t* a,
                                      uint32_t b0, uint32_t b1) {
    asm volatile(
        "mma.sync.aligned.m16n8k16.row.col.f32.f16.f16.f32 "
        "{%0,%1,%2,%3},{%4,%5,%6,%7},{%8,%9},{%0,%1,%2,%3};\n"
        : "+f"(c[0]), "+f"(c[1]), "+f"(c[2]), "+f"(c[3])
        : "r"(a[0]), "r"(a[1]), "r"(a[2]), "r"(a[3]), "r"(b0), "r"(b1));
}
__device__ __forceinline__ void ldsm4(uint32_t& r0, uint32_t& r1,
                                      uint32_t& r2, uint32_t& r3, uint32_t a) {
    asm volatile("ldmatrix.sync.aligned.m8n8.x4.shared.b16 {%0,%1,%2,%3}, [%4];"
                 : "=r"(r0), "=r"(r1), "=r"(r2), "=r"(r3) : "r"(a));
}
__device__ __forceinline__ void ldsm4t(uint32_t& r0, uint32_t& r1,
                                       uint32_t& r2, uint32_t& r3, uint32_t a) {
    asm volatile("ldmatrix.sync.aligned.m8n8.x4.trans.shared.b16 {%0,%1,%2,%3}, [%4];"
                 : "=r"(r0), "=r"(r1), "=r"(r2), "=r"(r3) : "r"(a));
}
__device__ __forceinline__ void cp_async16(uint32_t smem_dst, const void* gsrc) {
    asm volatile("cp.async.cg.shared.global [%0], [%1], 16;\n"
                 :: "r"(smem_dst), "l"(gsrc));
}
__device__ __forceinline__ void cp_commit() {
    asm volatile("cp.async.commit_group;\n");
}
template <int N>
__device__ __forceinline__ void cp_wait() {
    asm volatile("cp.async.wait_group %0;\n" :: "n"(N));
}
__device__ __forceinline__ float fast_ex2(float x) {
    float r;
    asm("ex2.approx.f32 %0, %1;" : "=f"(r) : "f"(x));
    return r;
}

// ---------------------------------------------------------------------------
// fp32 -> fp16 convert (one-shot)
// ---------------------------------------------------------------------------
__global__ void to_half(const float* __restrict__ in, __half* __restrict__ out,
                        int n4)
{
    int i = blockIdx.x * blockDim.x + threadIdx.x;
    if (i < n4) {
        float4 v = ((const float4*)in)[i];
        __half2* o = (__half2*)out + 2 * (size_t)i;
        o[0] = __floats2half2_rn(v.x, v.y);
        o[1] = __floats2half2_rn(v.z, v.w);
    }
}

// ---------------------------------------------------------------------------
// fp16 tensor-core GEMM + bias. BM=BN=128, BK=32, 4 warps (2x2),
// warp tile 64x64 (4.0 MMA/LDSM), 3-stage cp.async ring, 2 CTAs/SM.
// A rows 40 halfs (80B), B rows 136 halfs (272B): stride%128B = 16 ->
// conflict-free LDSM phases.
// ---------------------------------------------------------------------------
#define AS2 40
#define BS2 136
#define G_STAGES 3
#define A_STGH (128 * AS2)       // halfs per A stage (5120)
#define B_STGH (32 * BS2)        // halfs per B stage (4352)
#define GEMM_SMEM ((G_STAGES * (A_STGH + B_STGH)) * 2)   // 56832 B

template <bool HALF_OUT>
__global__ void __launch_bounds__(128, 2)
gemm_fp16(int M, int N, int K,
          const __half* __restrict__ A,
          const __half* __restrict__ W,
          const float* __restrict__ bias,
          void* __restrict__ Cv)
{
    extern __shared__ __half dsm[];
    __half* As = dsm;
    __half* Bs = dsm + G_STAGES * A_STGH;
    const uint32_t as_u32 = (uint32_t)__cvta_generic_to_shared(As);
    const uint32_t bs_u32 = (uint32_t)__cvta_generic_to_shared(Bs);

    const int tid  = threadIdx.x;
    const int wid  = tid >> 5;
    const int lane = tid & 31;
    const int gid  = lane >> 2;
    const int tig  = lane & 3;
    const int wm   = wid >> 1;   // 0..1 -> 64 rows
    const int wn   = wid & 1;    // 0..1 -> 64 cols

    const __half* Ab = A + (size_t)blockIdx.y * 128 * K;
    const __half* Wb = W + (size_t)blockIdx.x * 128;

    // cp.async maps (128 threads)
    const int aRow = tid;                   // 0..127, 4 chunks each
    const int bRow = tid >> 2;              // 0..31
    const int bC0  = (tid & 3) * 4;         // chunk 0..12

    // ldmatrix lane components
    const int j    = lane >> 3;             // matrix idx 0..3
    const int l7   = lane & 7;
    const int aLr  = (j & 1) * 8 + l7;      // A row-style
    const int aLc  = (j >> 1) * 8;
    const int bLk  = (j & 1) * 8 + l7;      // B trans k-row
    const int bLn  = (j >> 1) * 8;

    float c[4][8][4];
    #pragma unroll
    for (int i = 0; i < 4; i++)
        #pragma unroll
        for (int jj = 0; jj < 8; jj++)
            #pragma unroll
            for (int r = 0; r < 4; r++) c[i][jj][r] = 0.0f;

    const int T = K / 32;

    auto issue = [&](int kt, int s) {
        uint32_t ad = as_u32 + (uint32_t)(s * A_STGH + aRow * AS2) * 2;
        const __half* asrc = Ab + (size_t)aRow * K + kt * 32;
        #pragma unroll
        for (int i = 0; i < 4; i++)
            cp_async16(ad + i * 16, asrc + i * 8);
        uint32_t bd = bs_u32 + (uint32_t)(s * B_STGH + bRow * BS2) * 2;
        const __half* bsrc = Wb + (size_t)(kt * 32 + bRow) * N;
        #pragma unroll
        for (int i = 0; i < 4; i++)
            cp_async16(bd + (bC0 + i) * 16, bsrc + (bC0 + i) * 8);
        cp_commit();
    };

    issue(0, 0);
    issue(1, 1);

    for (int t = 0; t < T; t++) {
        if (t == T - 1) cp_wait<0>(); else cp_wait<1>();
        __syncthreads();
        if (t + 2 < T) issue(t + 2, (t + 2) % G_STAGES);

        const uint32_t abase = as_u32 + (uint32_t)((t % G_STAGES) * A_STGH) * 2;
        const uint32_t bbase = bs_u32 + (uint32_t)((t % G_STAGES) * B_STGH) * 2;

        #pragma unroll
        for (int kk = 0; kk < 32; kk += 16) {
            uint32_t a[4][4];
            #pragma unroll
            for (int mt = 0; mt < 4; mt++) {
                uint32_t ad = abase +
                    (uint32_t)((wm * 64 + mt * 16 + aLr) * AS2 + kk + aLc) * 2;
                ldsm4(a[mt][0], a[mt][1], a[mt][2], a[mt][3], ad);
            }
            #pragma unroll
            for (int g = 0; g < 4; g++) {
                uint32_t b0, b1, b2, b3;
                uint32_t bd = bbase +
                    (uint32_t)((kk + bLk) * BS2 + wn * 64 + g * 16 + bLn) * 2;
                ldsm4t(b0, b1, b2, b3, bd);
                #pragma unroll
                for (int mt = 0; mt < 4; mt++) {
                    mma16(c[mt][2 * g],     a[mt], b0, b1);
                    mma16(c[mt][2 * g + 1], a[mt], b2, b3);
                }
            }
        }
        __syncthreads();
    }

    // Epilogue
    #pragma unroll
    for (int mt = 0; mt < 4; mt++) {
        const int r = blockIdx.y * 128 + wm * 64 + mt * 16 + gid;
        #pragma unroll
        for (int nt = 0; nt < 8; nt++) {
            const int col = blockIdx.x * 128 + wn * 64 + nt * 8 + 2 * tig;
            float2 bv = *(const float2*)&bias[col];
            if (HALF_OUT) {
                __half* C = (__half*)Cv;
                *(__half2*)&C[(size_t)(r    ) * N + col] =
                    __floats2half2_rn(c[mt][nt][0] + bv.x, c[mt][nt][1] + bv.y);
                *(__half2*)&C[(size_t)(r + 8) * N + col] =
                    __floats2half2_rn(c[mt][nt][2] + bv.x, c[mt][nt][3] + bv.y);
            } else {
                float* C = (float*)Cv;
                float2 o0, o1;
                o0.x = c[mt][nt][0] + bv.x; o0.y = c[mt][nt][1] + bv.y;
                o1.x = c[mt][nt][2] + bv.x; o1.y = c[mt][nt][3] + bv.y;
                *(float2*)&C[(size_t)(r    ) * N + col] = o0;
                *(float2*)&C[(size_t)(r + 8) * N + col] = o1;
            }
        }
    }
}

// ---------------------------------------------------------------------------
// fp16 tensor-core flash attention. Br=128 (4 warps x 32 q-rows), Bc=64,
// m16n8k16, cp.async double-buffered K/V, dynamic smem (54KB), 2 CTAs/SM.
// Base-2 softmax (scale*log2e folded, ex2.approx).
// Layout: K[2][64*AT_S] | V[2][64*AT_S] | PQ[128*AT_S]
// ---------------------------------------------------------------------------
#define AT_S 72   // halfs per row (144B; %128B == 16 -> conflict-free)
#define KV_STGH (64 * AT_S)
#define ATTN_SMEM ((4 * KV_STGH + 128 * AT_S) * 2)   // 55296 B
#define SCALE_LOG2E 0.1803368801111244f   // 0.125 * log2(e)

__global__ void __launch_bounds__(128, 2)
attn_fp16(const __half* __restrict__ qkv, __half* __restrict__ y)
{
    extern __shared__ __half asm_[];
    __half* Ksm = asm_;
    __half* Vsm = asm_ + 2 * KV_STGH;
    __half* Pq  = asm_ + 4 * KV_STGH;
    const uint32_t k_u32 = (uint32_t)__cvta_generic_to_shared(Ksm);
    const uint32_t v_u32 = (uint32_t)__cvta_generic_to_shared(Vsm);
    const uint32_t p_u32 = (uint32_t)__cvta_generic_to_shared(Pq);

    const int b    = blockIdx.z;
    const int h    = blockIdx.y;
    const int q0   = blockIdx.x * 128;
    const int tid  = threadIdx.x;
    const int wid  = tid >> 5;
    const int lane = tid & 31;
    const int gid  = lane >> 2;
    const int tig  = lane & 3;

    const int sRow = tid >> 1;          // K/V load row 0..63
    const int sC0  = (tid & 1) * 4;

    const int j   = lane >> 3;
    const int l7  = lane & 7;
    const int aLr = (j & 1) * 8 + l7;
    const int aLc = (j >> 1) * 8;
    const int nLr = (j >> 1) * 8 + l7;
    const int nLc = (j & 1) * 8;
    const int vLk = (j & 1) * 8 + l7;
    const int vLn = (j >> 1) * 8;

    auto issue_q = [&]() {
        const __half* src = qkv + ((size_t)(b * SEQ + q0 + tid)) * (3 * DMODEL)
                          + h * HD;
        uint32_t qd = p_u32 + (uint32_t)(tid * AT_S) * 2;
        #pragma unroll
        for (int i = 0; i < 8; i++)
            cp_async16(qd + i * 16, src + i * 8);
        cp_commit();
    };
    auto issue_kv = [&](int kt, int s) {
        const __half* src = qkv + ((size_t)(b * SEQ + kt + sRow)) * (3 * DMODEL)
                          + DMODEL + h * HD;
        uint32_t kd = k_u32 + (uint32_t)(s * KV_STGH + sRow * AT_S) * 2;
        uint32_t vd = v_u32 + (uint32_t)(s * KV_STGH + sRow * AT_S) * 2;
        #pragma unroll
        for (int i = 0; i < 4; i++) {
            cp_async16(kd + (sC0 + i) * 16, src + (sC0 + i) * 8);
            cp_async16(vd + (sC0 + i) * 16, src + DMODEL + (sC0 + i) * 8);
        }
        cp_commit();
    };

    issue_q();
    issue_kv(0, 0);
    cp_wait<0>();
    __syncthreads();

    // Q fragments resident: 4 k16 slabs x 2 m-tiles
    uint32_t qa[4][2][4];
    #pragma unroll
    for (int sl = 0; sl < 4; sl++)
        #pragma unroll
        for (int mt = 0; mt < 2; mt++) {
            uint32_t ad = p_u32 +
                (uint32_t)((wid * 32 + mt * 16 + aLr) * AT_S + sl * 16 + aLc) * 2;
            ldsm4(qa[sl][mt][0], qa[sl][mt][1], qa[sl][mt][2], qa[sl][mt][3], ad);
        }

    float o[2][8][4];
    #pragma unroll
    for (int mt = 0; mt < 2; mt++)
        #pragma unroll
        for (int n = 0; n < 8; n++)
            #pragma unroll
            for (int q = 0; q < 4; q++) o[mt][n][q] = 0.0f;
    float m[4] = {-1e30f, -1e30f, -1e30f, -1e30f};
    float l[4] = {0.0f, 0.0f, 0.0f, 0.0f};

    const int NT = SEQ / 64;
    for (int t = 0; t < NT; t++) {
        if (t > 0) {
            cp_wait<0>();
            __syncthreads();
        }
        if (t + 1 < NT) issue_kv((t + 1) * 64, (t + 1) & 1);

        const uint32_t kb = k_u32 + (uint32_t)((t & 1) * KV_STGH) * 2;
        const uint32_t vb = v_u32 + (uint32_t)((t & 1) * KV_STGH) * 2;

        // ---- S = Q K^T ----
        float s[2][8][4];
        #pragma unroll
        for (int mt = 0; mt < 2; mt++)
            #pragma unroll
            for (int n = 0; n < 8; n++)
                #pragma unroll
                for (int q = 0; q < 4; q++) s[mt][n][q] = 0.0f;
        #pragma unroll
        for (int sl = 0; sl < 4; sl++) {
            const int kk = sl * 16;
            #pragma unroll
            for (int g = 0; g < 4; g++) {
                uint32_t r0, r1, r2, r3;
                uint32_t kd = kb + (uint32_t)((g * 16 + nLr) * AT_S + kk + nLc) * 2;
                ldsm4(r0, r1, r2, r3, kd);
                #pragma unroll
                for (int mt = 0; mt < 2; mt++) {
                    mma16(s[mt][2 * g],     qa[sl][mt], r0, r1);
                    mma16(s[mt][2 * g + 1], qa[sl][mt], r2, r3);
                }
            }
        }

        // ---- online softmax (base-2), 4 row groups ----
        #pragma unroll
        for (int mt = 0; mt < 2; mt++) {
            float mx0 = -1e30f, mx1 = -1e30f;
            #pragma unroll
            for (int n = 0; n < 8; n++) {
                s[mt][n][0] *= SCALE_LOG2E; s[mt][n][1] *= SCALE_LOG2E;
                s[mt][n][2] *= SCALE_LOG2E; s[mt][n][3] *= SCALE_LOG2E;
                mx0 = fmaxf(mx0, fmaxf(s[mt][n][0], s[mt][n][1]));
                mx1 = fmaxf(mx1, fmaxf(s[mt][n][2], s[mt][n][3]));
            }
            mx0 = fmaxf(mx0, __shfl_xor_sync(0xffffffffu, mx0, 1));
            mx0 = fmaxf(mx0, __shfl_xor_sync(0xffffffffu, mx0, 2));
            mx1 = fmaxf(mx1, __shfl_xor_sync(0xffffffffu, mx1, 1));
            mx1 = fmaxf(mx1, __shfl_xor_sync(0xffffffffu, mx1, 2));
            const float mn0 = fmaxf(m[2 * mt],     mx0);
            const float mn1 = fmaxf(m[2 * mt + 1], mx1);
            const float al0 = fast_ex2(m[2 * mt]     - mn0);
            const float al1 = fast_ex2(m[2 * mt + 1] - mn1);
            m[2 * mt] = mn0; m[2 * mt + 1] = mn1;

            float sum0 = 0.0f, sum1 = 0.0f;
            #pragma unroll
            for (int n = 0; n < 8; n++) {
                s[mt][n][0] = fast_ex2(s[mt][n][0] - mn0); sum0 += s[mt][n][0];
                s[mt][n][1] = fast_ex2(s[mt][n][1] - mn0); sum0 += s[mt][n][1];
                s[mt][n][2] = fast_ex2(s[mt][n][2] - mn1); sum1 += s[mt][n][2];
                s[mt][n][3] = fast_ex2(s[mt][n][3] - mn1); sum1 += s[mt][n][3];
            }
            sum0 += __shfl_xor_sync(0xffffffffu, sum0, 1);
            sum0 += __shfl_xor_sync(0xffffffffu, sum0, 2);
            sum1 += __shfl_xor_sync(0xffffffffu, sum1, 1);
            sum1 += __shfl_xor_sync(0xffffffffu, sum1, 2);
            l[2 * mt]     = l[2 * mt]     * al0 + sum0;
            l[2 * mt + 1] = l[2 * mt + 1] * al1 + sum1;

            #pragma unroll
            for (int n = 0; n < 8; n++) {
                o[mt][n][0] *= al0; o[mt][n][1] *= al0;
                o[mt][n][2] *= al1; o[mt][n][3] *= al1;
            }

            // P -> smem (fp16), warp-private rows
            const int pr = wid * 32 + mt * 16 + gid;
            #pragma unroll
            for (int n = 0; n < 8; n++) {
                *(__half2*)&Pq[(pr    ) * AT_S + n * 8 + 2 * tig] =
                    __floats2half2_rn(s[mt][n][0], s[mt][n][1]);
                *(__half2*)&Pq[(pr + 8) * AT_S + n * 8 + 2 * tig] =
                    __floats2half2_rn(s[mt][n][2], s[mt][n][3]);
            }
        }
        __syncwarp();

        // ---- O += P @ V ----
        #pragma unroll
        for (int sl = 0; sl < 4; sl++) {
            const int kk = sl * 16;
            uint32_t pa[2][4];
            #pragma unroll
            for (int mt = 0; mt < 2; mt++) {
                uint32_t pd = p_u32 +
                    (uint32_t)((wid * 32 + mt * 16 + aLr) * AT_S + kk + aLc) * 2;
                ldsm4(pa[mt][0], pa[mt][1], pa[mt][2], pa[mt][3], pd);
            }
            #pragma unroll
            for (int g = 0; g < 4; g++) {
                uint32_t r0, r1, r2, r3;
                uint32_t vd = vb + (uint32_t)((kk + vLk) * AT_S + g * 16 + vLn) * 2;
                ldsm4t(r0, r1, r2, r3, vd);
                #pragma unroll
                for (int mt = 0; mt < 2; mt++) {
                    mma16(o[mt][2 * g],     pa[mt], r0, r1);
                    mma16(o[mt][2 * g + 1], pa[mt], r2, r3);
                }
            }
        }
    }

    // ---- normalize + write y (fp16) ----
    #pragma unroll
    for (int mt = 0; mt < 2; mt++) {
        const float i0 = 1.0f / l[2 * mt];
        const float i1 = 1.0f / l[2 * mt + 1];
        __half* yp = y + ((size_t)(b * SEQ + q0 + wid * 32 + mt * 16 + gid)) * DMODEL
                   + h * HD;
        #pragma unroll
        for (int n = 0; n < 8; n++) {
            const int cc = n * 8 + 2 * tig;
            *(__half2*)&yp[cc] =
                __floats2half2_rn(o[mt][n][0] * i0, o[mt][n][1] * i0);
            *(__half2*)&yp[8 * DMODEL + cc] =
                __floats2half2_rn(o[mt][n][2] * i1, o[mt][n][3] * i1);
        }
    }
}

// ---------------------------------------------------------------------------
// Launch
// ---------------------------------------------------------------------------
extern "C" void kernel_launch(void* const* d_in, const int* in_sizes, int n_in,
                              void* d_out, int out_size)
{
    const float* x     = (const float*)d_in[0];
    const float* Wqkv  = (const float*)d_in[1];
    const float* bqkv  = (const float*)d_in[2];
    const float* Wproj = (const float*)d_in[3];
    const float* bproj = (const float*)d_in[4];
    float* out = (float*)d_out;

    __half *qkv = nullptr, *y = nullptr, *xh = nullptr, *wq = nullptr, *wp = nullptr;
    cudaGetSymbolAddress((void**)&qkv, g_qkv);
    cudaGetSymbolAddress((void**)&y,   g_y);
    cudaGetSymbolAddress((void**)&xh,  g_x);
    cudaGetSymbolAddress((void**)&wq,  g_wq);
    cudaGetSymbolAddress((void**)&wp,  g_wp);

    cudaFuncSetAttribute(gemm_fp16<true>,
                         cudaFuncAttributeMaxDynamicSharedMemorySize, GEMM_SMEM);
    cudaFuncSetAttribute(gemm_fp16<false>,
                         cudaFuncAttributeMaxDynamicSharedMemorySize, GEMM_SMEM);
    cudaFuncSetAttribute(attn_fp16,
                         cudaFuncAttributeMaxDynamicSharedMemorySize, ATTN_SMEM);

    // 0) convert inputs/weights to fp16
    {
        int n4;
        n4 = MTOT * DMODEL / 4;
        to_half<<<(n4 + 255) / 256, 256>>>(x, xh, n4);
        n4 = DMODEL * 3 * DMODEL / 4;
        to_half<<<(n4 + 255) / 256, 256>>>(Wqkv, wq, n4);
        n4 = DMODEL * DMODEL / 4;
        to_half<<<(n4 + 255) / 256, 256>>>(Wproj, wp, n4);
    }

    // 1) QKV projection -> fp16 qkv
    gemm_fp16<true><<<dim3(3 * DMODEL / 128, MTOT / 128), 128, GEMM_SMEM>>>(
        MTOT, 3 * DMODEL, DMODEL, xh, wq, bqkv, qkv);

    // 2) flash attention -> fp16 y
    attn_fp16<<<dim3(SEQ / 128, NHEAD, BATCH), 128, ATTN_SMEM>>>(qkv, y);

    // 3) output projection -> fp32 out
    gemm_fp16<false><<<dim3(DMODEL / 128, MTOT / 128), 128, GEMM_SMEM>>>(
        MTOT, DMODEL, DMODEL, y, wp, bproj, out);
}

// round 14
// speedup vs baseline: 7.2229x; 1.0990x over previous
#include <cuda_runtime.h>
#include <cuda_fp16.h>
#include <math.h>
#include <stdint.h>

// Problem constants
#define BATCH  4
#define SEQ    2048
#define DMODEL 1024
#define NHEAD  16
#define HD     64
#define MTOT   (BATCH * SEQ)   // 8192

// Scratch (allocation-free: __device__ globals) — fp16 activations/weights
__device__ __half g_qkv[(size_t)BATCH * SEQ * 3 * DMODEL];  // [B,T,3D]
__device__ __half g_y  [(size_t)BATCH * SEQ * DMODEL];      // [B,T,D]
__device__ __half g_x  [(size_t)MTOT * DMODEL];
__device__ __half g_wq [(size_t)DMODEL * 3 * DMODEL];
__device__ __half g_wp [(size_t)DMODEL * DMODEL];

// ---------------------------------------------------------------------------
// Helpers
// ---------------------------------------------------------------------------
__device__ __forceinline__ void mma16(float* c, const uint32_t* a,
                                      uint32_t b0, uint32_t b1) {
    asm volatile(
        "mma.sync.aligned.m16n8k16.row.col.f32.f16.f16.f32 "
        "{%0,%1,%2,%3},{%4,%5,%6,%7},{%8,%9},{%0,%1,%2,%3};\n"
        : "+f"(c[0]), "+f"(c[1]), "+f"(c[2]), "+f"(c[3])
        : "r"(a[0]), "r"(a[1]), "r"(a[2]), "r"(a[3]), "r"(b0), "r"(b1));
}
__device__ __forceinline__ void ldsm4(uint32_t& r0, uint32_t& r1,
                                      uint32_t& r2, uint32_t& r3, uint32_t a) {
    asm volatile("ldmatrix.sync.aligned.m8n8.x4.shared.b16 {%0,%1,%2,%3}, [%4];"
                 : "=r"(r0), "=r"(r1), "=r"(r2), "=r"(r3) : "r"(a));
}
__device__ __forceinline__ void ldsm4t(uint32_t& r0, uint32_t& r1,
                                       uint32_t& r2, uint32_t& r3, uint32_t a) {
    asm volatile("ldmatrix.sync.aligned.m8n8.x4.trans.shared.b16 {%0,%1,%2,%3}, [%4];"
                 : "=r"(r0), "=r"(r1), "=r"(r2), "=r"(r3) : "r"(a));
}
__device__ __forceinline__ void cp_async16(uint32_t smem_dst, const void* gsrc) {
    asm volatile("cp.async.cg.shared.global [%0], [%1], 16;\n"
                 :: "r"(smem_dst), "l"(gsrc));
}
__device__ __forceinline__ void cp_commit() {
    asm volatile("cp.async.commit_group;\n");
}
template <int N>
__device__ __forceinline__ void cp_wait() {
    asm volatile("cp.async.wait_group %0;\n" :: "n"(N));
}
__device__ __forceinline__ float fast_ex2(float x) {
    float r;
    asm("ex2.approx.f32 %0, %1;" : "=f"(r) : "f"(x));
    return r;
}
// Packed half2 exp2: convert two fp32 deltas to half2, one MUFU op for both.
__device__ __forceinline__ uint32_t ex2_h2(float a, float b) {
    __half2 h = __floats2half2_rn(a, b);
    uint32_t u = *reinterpret_cast<uint32_t*>(&h);
    uint32_t r;
    asm("ex2.approx.f16x2 %0, %1;" : "=r"(r) : "r"(u));
    return r;
}

// ---------------------------------------------------------------------------
// fp32 -> fp16 convert (one-shot)
// ---------------------------------------------------------------------------
__global__ void to_half(const float* __restrict__ in, __half* __restrict__ out,
                        int n4)
{
    int i = blockIdx.x * blockDim.x + threadIdx.x;
    if (i < n4) {
        float4 v = ((const float4*)in)[i];
        __half2* o = (__half2*)out + 2 * (size_t)i;
        o[0] = __floats2half2_rn(v.x, v.y);
        o[1] = __floats2half2_rn(v.z, v.w);
    }
}

// ---------------------------------------------------------------------------
// fp16 tensor-core GEMM + bias. BM=BN=128, BK=32, 8 warps (2x4),
// warp tile 64x32, m16n8k16, 4-stage cp.async ring (&3 slots), 2 CTAs/SM.
// A rows 40 halfs (80B), B rows 136 halfs (272B): stride%128B = 16 ->
// conflict-free LDSM phases. One barrier per K-tile.
// ---------------------------------------------------------------------------
#define AS2 40
#define BS2 136
#define G_STAGES 4
#define A_STGH (128 * AS2)       // halfs per A stage (5120)
#define B_STGH (32 * BS2)        // halfs per B stage (4352)
#define GEMM_SMEM ((G_STAGES * (A_STGH + B_STGH)) * 2)   // 75776 B

template <bool HALF_OUT>
__global__ void __launch_bounds__(256, 2)
gemm_fp16(int M, int N, int K,
          const __half* __restrict__ A,
          const __half* __restrict__ W,
          const float* __restrict__ bias,
          void* __restrict__ Cv)
{
    extern __shared__ __half dsm[];
    __half* As = dsm;
    __half* Bs = dsm + G_STAGES * A_STGH;
    const uint32_t as_u32 = (uint32_t)__cvta_generic_to_shared(As);
    const uint32_t bs_u32 = (uint32_t)__cvta_generic_to_shared(Bs);

    const int tid  = threadIdx.x;
    const int wid  = tid >> 5;
    const int lane = tid & 31;
    const int gid  = lane >> 2;
    const int tig  = lane & 3;
    const int wm   = wid >> 2;   // 0..1 -> 64 rows
    const int wn   = wid & 3;    // 0..3 -> 32 cols

    const __half* Ab = A + (size_t)blockIdx.y * 128 * K;
    const __half* Wb = W + (size_t)blockIdx.x * 128;

    // cp.async maps (256 threads)
    const int aRow = tid >> 1;              // 0..127
    const int aC0  = (tid & 1) * 2;         // chunk 0..3 (16B each)
    const int bRow = tid >> 3;              // 0..31
    const int bC0  = (tid & 7) * 2;         // chunk 0..15

    // ldmatrix lane components
    const int j    = lane >> 3;             // matrix idx 0..3
    const int l7   = lane & 7;
    const int aLr  = (j & 1) * 8 + l7;      // A row-style
    const int aLc  = (j >> 1) * 8;
    const int bLk  = (j & 1) * 8 + l7;      // B trans k-row
    const int bLn  = (j >> 1) * 8;

    float c[4][4][4];
    #pragma unroll
    for (int i = 0; i < 4; i++)
        #pragma unroll
        for (int jj = 0; jj < 4; jj++)
            #pragma unroll
            for (int r = 0; r < 4; r++) c[i][jj][r] = 0.0f;

    const int T = K / 32;

    auto issue = [&](int kt, int s) {
        uint32_t ad = as_u32 + (uint32_t)(s * A_STGH + aRow * AS2) * 2;
        const __half* asrc = Ab + (size_t)aRow * K + kt * 32;
        #pragma unroll
        for (int i = 0; i < 2; i++)
            cp_async16(ad + (aC0 + i) * 16, asrc + (aC0 + i) * 8);
        uint32_t bd = bs_u32 + (uint32_t)(s * B_STGH + bRow * BS2) * 2;
        const __half* bsrc = Wb + (size_t)(kt * 32 + bRow) * N;
        #pragma unroll
        for (int i = 0; i < 2; i++)
            cp_async16(bd + (bC0 + i) * 16, bsrc + (bC0 + i) * 8);
        cp_commit();
    };

    issue(0, 0);
    issue(1, 1);
    issue(2, 2);

    for (int t = 0; t < T; t++) {
        // ensure tile t landed (this thread), then all threads
        if (t + 2 < T)      cp_wait<2>();
        else if (t + 1 < T) cp_wait<1>();
        else                cp_wait<0>();
        __syncthreads();    // tile t visible; all warps done with tile t-1
        if (t + 3 < T) issue(t + 3, (t + 3) & 3);

        const uint32_t abase = as_u32 + (uint32_t)((t & 3) * A_STGH) * 2;
        const uint32_t bbase = bs_u32 + (uint32_t)((t & 3) * B_STGH) * 2;

        #pragma unroll
        for (int kk = 0; kk < 32; kk += 16) {
            uint32_t a[4][4];
            #pragma unroll
            for (int mt = 0; mt < 4; mt++) {
                uint32_t ad = abase +
                    (uint32_t)((wm * 64 + mt * 16 + aLr) * AS2 + kk + aLc) * 2;
                ldsm4(a[mt][0], a[mt][1], a[mt][2], a[mt][3], ad);
            }
            uint32_t bg[2][4];
            #pragma unroll
            for (int g = 0; g < 2; g++) {
                uint32_t bd = bbase +
                    (uint32_t)((kk + bLk) * BS2 + wn * 32 + g * 16 + bLn) * 2;
                ldsm4t(bg[g][0], bg[g][1], bg[g][2], bg[g][3], bd);
            }
            #pragma unroll
            for (int mt = 0; mt < 4; mt++)
                #pragma unroll
                for (int g = 0; g < 2; g++) {
                    mma16(c[mt][2 * g],     a[mt], bg[g][0], bg[g][1]);
                    mma16(c[mt][2 * g + 1], a[mt], bg[g][2], bg[g][3]);
                }
        }
    }

    // Epilogue
    #pragma unroll
    for (int mt = 0; mt < 4; mt++) {
        const int r = blockIdx.y * 128 + wm * 64 + mt * 16 + gid;
        #pragma unroll
        for (int nt = 0; nt < 4; nt++) {
            const int col = blockIdx.x * 128 + wn * 32 + nt * 8 + 2 * tig;
            float2 bv = *(const float2*)&bias[col];
            if (HALF_OUT) {
                __half* C = (__half*)Cv;
                *(__half2*)&C[(size_t)(r    ) * N + col] =
                    __floats2half2_rn(c[mt][nt][0] + bv.x, c[mt][nt][1] + bv.y);
                *(__half2*)&C[(size_t)(r + 8) * N + col] =
                    __floats2half2_rn(c[mt][nt][2] + bv.x, c[mt][nt][3] + bv.y);
            } else {
                float* C = (float*)Cv;
                float2 o0, o1;
                o0.x = c[mt][nt][0] + bv.x; o0.y = c[mt][nt][1] + bv.y;
                o1.x = c[mt][nt][2] + bv.x; o1.y = c[mt][nt][3] + bv.y;
                *(float2*)&C[(size_t)(r    ) * N + col] = o0;
                *(float2*)&C[(size_t)(r + 8) * N + col] = o1;
            }
        }
    }
}

// ---------------------------------------------------------------------------
// fp16 tensor-core flash attention. Br=128 (4 warps x 32 q-rows), Bc=64,
// m16n8k16, cp.async double-buffered K/V, dynamic smem (54KB), 2 CTAs/SM.
// Base-2 softmax with ex2.approx.f16x2 (one MUFU op per half2 pair; result
// IS the fp16 P value -> stored directly).
// Layout: K[2][64*AT_S] | V[2][64*AT_S] | PQ[128*AT_S]
// ---------------------------------------------------------------------------
#define AT_S 72   // halfs per row (144B; %128B == 16 -> conflict-free)
#define KV_STGH (64 * AT_S)
#define ATTN_SMEM ((4 * KV_STGH + 128 * AT_S) * 2)   // 55296 B
#define SCALE_LOG2E 0.1803368801111244f   // 0.125 * log2(e)

__global__ void __launch_bounds__(128, 2)
attn_fp16(const __half* __restrict__ qkv, __half* __restrict__ y)
{
    extern __shared__ __half asm_[];
    __half* Ksm = asm_;
    __half* Vsm = asm_ + 2 * KV_STGH;
    __half* Pq  = asm_ + 4 * KV_STGH;
    const uint32_t k_u32 = (uint32_t)__cvta_generic_to_shared(Ksm);
    const uint32_t v_u32 = (uint32_t)__cvta_generic_to_shared(Vsm);
    const uint32_t p_u32 = (uint32_t)__cvta_generic_to_shared(Pq);

    const int b    = blockIdx.z;
    const int h    = blockIdx.y;
    const int q0   = blockIdx.x * 128;
    const int tid  = threadIdx.x;
    const int wid  = tid >> 5;
    const int lane = tid & 31;
    const int gid  = lane >> 2;
    const int tig  = lane & 3;

    const int sRow = tid >> 1;          // K/V load row 0..63
    const int sC0  = (tid & 1) * 4;

    const int j   = lane >> 3;
    const int l7  = lane & 7;
    const int aLr = (j & 1) * 8 + l7;
    const int aLc = (j >> 1) * 8;
    const int nLr = (j >> 1) * 8 + l7;
    const int nLc = (j & 1) * 8;
    const int vLk = (j & 1) * 8 + l7;
    const int vLn = (j >> 1) * 8;

    auto issue_q = [&]() {
        const __half* src = qkv + ((size_t)(b * SEQ + q0 + tid)) * (3 * DMODEL)
                          + h * HD;
        uint32_t qd = p_u32 + (uint32_t)(tid * AT_S) * 2;
        #pragma unroll
        for (int i = 0; i < 8; i++)
            cp_async16(qd + i * 16, src + i * 8);
        cp_commit();
    };
    auto issue_kv = [&](int kt, int s) {
        const __half* src = qkv + ((size_t)(b * SEQ + kt + sRow)) * (3 * DMODEL)
                          + DMODEL + h * HD;
        uint32_t kd = k_u32 + (uint32_t)(s * KV_STGH + sRow * AT_S) * 2;
        uint32_t vd = v_u32 + (uint32_t)(s * KV_STGH + sRow * AT_S) * 2;
        #pragma unroll
        for (int i = 0; i < 4; i++) {
            cp_async16(kd + (sC0 + i) * 16, src + (sC0 + i) * 8);
            cp_async16(vd + (sC0 + i) * 16, src + DMODEL + (sC0 + i) * 8);
        }
        cp_commit();
    };

    issue_q();
    issue_kv(0, 0);
    cp_wait<0>();
    __syncthreads();

    // Q fragments resident: 4 k16 slabs x 2 m-tiles
    uint32_t qa[4][2][4];
    #pragma unroll
    for (int sl = 0; sl < 4; sl++)
        #pragma unroll
        for (int mt = 0; mt < 2; mt++) {
            uint32_t ad = p_u32 +
                (uint32_t)((wid * 32 + mt * 16 + aLr) * AT_S + sl * 16 + aLc) * 2;
            ldsm4(qa[sl][mt][0], qa[sl][mt][1], qa[sl][mt][2], qa[sl][mt][3], ad);
        }

    float o[2][8][4];
    #pragma unroll
    for (int mt = 0; mt < 2; mt++)
        #pragma unroll
        for (int n = 0; n < 8; n++)
            #pragma unroll
            for (int q = 0; q < 4; q++) o[mt][n][q] = 0.0f;
    float m[4] = {-1e30f, -1e30f, -1e30f, -1e30f};
    float l[4] = {0.0f, 0.0f, 0.0f, 0.0f};

    const int NT = SEQ / 64;
    for (int t = 0; t < NT; t++) {
        if (t > 0) {
            cp_wait<0>();
            __syncthreads();
        }
        if (t + 1 < NT) issue_kv((t + 1) * 64, (t + 1) & 1);

        const uint32_t kb = k_u32 + (uint32_t)((t & 1) * KV_STGH) * 2;
        const uint32_t vb = v_u32 + (uint32_t)((t & 1) * KV_STGH) * 2;

        // ---- S = Q K^T ----
        float s[2][8][4];
        #pragma unroll
        for (int mt = 0; mt < 2; mt++)
            #pragma unroll
            for (int n = 0; n < 8; n++)
                #pragma unroll
                for (int q = 0; q < 4; q++) s[mt][n][q] = 0.0f;
        #pragma unroll
        for (int sl = 0; sl < 4; sl++) {
            const int kk = sl * 16;
            #pragma unroll
            for (int g = 0; g < 4; g++) {
                uint32_t r0, r1, r2, r3;
                uint32_t kd = kb + (uint32_t)((g * 16 + nLr) * AT_S + kk + nLc) * 2;
                ldsm4(r0, r1, r2, r3, kd);
                #pragma unroll
                for (int mt = 0; mt < 2; mt++) {
                    mma16(s[mt][2 * g],     qa[sl][mt], r0, r1);
                    mma16(s[mt][2 * g + 1], qa[sl][mt], r2, r3);
                }
            }
        }

        // ---- online softmax (base-2, f16x2 exp), 4 row groups ----
        #pragma unroll
        for (int mt = 0; mt < 2; mt++) {
            float mx0 = -1e30f, mx1 = -1e30f;
            #pragma unroll
            for (int n = 0; n < 8; n++) {
                s[mt][n][0] *= SCALE_LOG2E; s[mt][n][1] *= SCALE_LOG2E;
                s[mt][n][2] *= SCALE_LOG2E; s[mt][n][3] *= SCALE_LOG2E;
                mx0 = fmaxf(mx0, fmaxf(s[mt][n][0], s[mt][n][1]));
                mx1 = fmaxf(mx1, fmaxf(s[mt][n][2], s[mt][n][3]));
            }
            mx0 = fmaxf(mx0, __shfl_xor_sync(0xffffffffu, mx0, 1));
            mx0 = fmaxf(mx0, __shfl_xor_sync(0xffffffffu, mx0, 2));
            mx1 = fmaxf(mx1, __shfl_xor_sync(0xffffffffu, mx1, 1));
            mx1 = fmaxf(mx1, __shfl_xor_sync(0xffffffffu, mx1, 2));
            const float mn0 = fmaxf(m[2 * mt],     mx0);
            const float mn1 = fmaxf(m[2 * mt + 1], mx1);
            const float al0 = fast_ex2(m[2 * mt]     - mn0);
            const float al1 = fast_ex2(m[2 * mt + 1] - mn1);
            m[2 * mt] = mn0; m[2 * mt + 1] = mn1;

            // exp2 in packed fp16; result IS fp16 P -> store directly
            const int pr = wid * 32 + mt * 16 + gid;
            float sum0 = 0.0f, sum1 = 0.0f;
            #pragma unroll
            for (int n = 0; n < 8; n++) {
                uint32_t p0 = ex2_h2(s[mt][n][0] - mn0, s[mt][n][1] - mn0);
                uint32_t p1 = ex2_h2(s[mt][n][2] - mn1, s[mt][n][3] - mn1);
                *(uint32_t*)&Pq[(pr    ) * AT_S + n * 8 + 2 * tig] = p0;
                *(uint32_t*)&Pq[(pr + 8) * AT_S + n * 8 + 2 * tig] = p1;
                float2 f0 = __half22float2(*reinterpret_cast<__half2*>(&p0));
                float2 f1 = __half22float2(*reinterpret_cast<__half2*>(&p1));
                sum0 += f0.x + f0.y;
                sum1 += f1.x + f1.y;
            }
            sum0 += __shfl_xor_sync(0xffffffffu, sum0, 1);
            sum0 += __shfl_xor_sync(0xffffffffu, sum0, 2);
            sum1 += __shfl_xor_sync(0xffffffffu, sum1, 1);
            sum1 += __shfl_xor_sync(0xffffffffu, sum1, 2);
            l[2 * mt]     = l[2 * mt]     * al0 + sum0;
            l[2 * mt + 1] = l[2 * mt + 1] * al1 + sum1;

            #pragma unroll
            for (int n = 0; n < 8; n++) {
                o[mt][n][0] *= al0; o[mt][n][1] *= al0;
                o[mt][n][2] *= al1; o[mt][n][3] *= al1;
            }
        }
        __syncwarp();

        // ---- O += P @ V ----
        #pragma unroll
        for (int sl = 0; sl < 4; sl++) {
            const int kk = sl * 16;
            uint32_t pa[2][4];
            #pragma unroll
            for (int mt = 0; mt < 2; mt++) {
                uint32_t pd = p_u32 +
                    (uint32_t)((wid * 32 + mt * 16 + aLr) * AT_S + kk + aLc) * 2;
                ldsm4(pa[mt][0], pa[mt][1], pa[mt][2], pa[mt][3], pd);
            }
            #pragma unroll
            for (int g = 0; g < 4; g++) {
                uint32_t r0, r1, r2, r3;
                uint32_t vd = vb + (uint32_t)((kk + vLk) * AT_S + g * 16 + vLn) * 2;
                ldsm4t(r0, r1, r2, r3, vd);
                #pragma unroll
                for (int mt = 0; mt < 2; mt++) {
                    mma16(o[mt][2 * g],     pa[mt], r0, r1);
                    mma16(o[mt][2 * g + 1], pa[mt], r2, r3);
                }
            }
        }
    }

    // ---- normalize + write y (fp16) ----
    #pragma unroll
    for (int mt = 0; mt < 2; mt++) {
        const float i0 = 1.0f / l[2 * mt];
        const float i1 = 1.0f / l[2 * mt + 1];
        __half* yp = y + ((size_t)(b * SEQ + q0 + wid * 32 + mt * 16 + gid)) * DMODEL
                   + h * HD;
        #pragma unroll
        for (int n = 0; n < 8; n++) {
            const int cc = n * 8 + 2 * tig;
            *(__half2*)&yp[cc] =
                __floats2half2_rn(o[mt][n][0] * i0, o[mt][n][1] * i0);
            *(__half2*)&yp[8 * DMODEL + cc] =
                __floats2half2_rn(o[mt][n][2] * i1, o[mt][n][3] * i1);
        }
    }
}

// ---------------------------------------------------------------------------
// Launch
// ---------------------------------------------------------------------------
extern "C" void kernel_launch(void* const* d_in, const int* in_sizes, int n_in,
                              void* d_out, int out_size)
{
    const float* x     = (const float*)d_in[0];
    const float* Wqkv  = (const float*)d_in[1];
    const float* bqkv  = (const float*)d_in[2];
    const float* Wproj = (const float*)d_in[3];
    const float* bproj = (const float*)d_in[4];
    float* out = (float*)d_out;

    __half *qkv = nullptr, *y = nullptr, *xh = nullptr, *wq = nullptr, *wp = nullptr;
    cudaGetSymbolAddress((void**)&qkv, g_qkv);
    cudaGetSymbolAddress((void**)&y,   g_y);
    cudaGetSymbolAddress((void**)&xh,  g_x);
    cudaGetSymbolAddress((void**)&wq,  g_wq);
    cudaGetSymbolAddress((void**)&wp,  g_wp);

    cudaFuncSetAttribute(gemm_fp16<true>,
                         cudaFuncAttributeMaxDynamicSharedMemorySize, GEMM_SMEM);
    cudaFuncSetAttribute(gemm_fp16<false>,
                         cudaFuncAttributeMaxDynamicSharedMemorySize, GEMM_SMEM);
    cudaFuncSetAttribute(attn_fp16,
                         cudaFuncAttributeMaxDynamicSharedMemorySize, ATTN_SMEM);

    // 0) convert inputs/weights to fp16
    {
        int n4;
        n4 = MTOT * DMODEL / 4;
        to_half<<<(n4 + 255) / 256, 256>>>(x, xh, n4);
        n4 = DMODEL * 3 * DMODEL / 4;
        to_half<<<(n4 + 255) / 256, 256>>>(Wqkv, wq, n4);
        n4 = DMODEL * DMODEL / 4;
        to_half<<<(n4 + 255) / 256, 256>>>(Wproj, wp, n4);
    }

    // 1) QKV projection -> fp16 qkv
    gemm_fp16<true><<<dim3(3 * DMODEL / 128, MTOT / 128), 256, GEMM_SMEM>>>(
        MTOT, 3 * DMODEL, DMODEL, xh, wq, bqkv, qkv);

    // 2) flash attention -> fp16 y
    attn_fp16<<<dim3(SEQ / 128, NHEAD, BATCH), 128, ATTN_SMEM>>>(qkv, y);

    // 3) output projection -> fp32 out
    gemm_fp16<false><<<dim3(DMODEL / 128, MTOT / 128), 256, GEMM_SMEM>>>(
        MTOT, DMODEL, DMODEL, y, wp, bproj, out);
}

// round 15
// speedup vs baseline: 7.5329x; 1.0429x over previous
#include <cuda_runtime.h>
#include <cuda_fp16.h>
#include <math.h>
#include <stdint.h>

// Problem constants
#define BATCH  4
#define SEQ    2048
#define DMODEL 1024
#define NHEAD  16
#define HD     64
#define MTOT   (BATCH * SEQ)   // 8192

// Scratch (allocation-free: __device__ globals) — fp16 activations/weights
__device__ __half g_qkv[(size_t)BATCH * SEQ * 3 * DMODEL];  // [B,T,3D]
__device__ __half g_y  [(size_t)BATCH * SEQ * DMODEL];      // [B,T,D]
__device__ __half g_x  [(size_t)MTOT * DMODEL];
__device__ __half g_wq [(size_t)DMODEL * 3 * DMODEL];
__device__ __half g_wp [(size_t)DMODEL * DMODEL];

// ---------------------------------------------------------------------------
// Helpers
// ---------------------------------------------------------------------------
__device__ __forceinline__ void mma16(float* c, const uint32_t* a,
                                      uint32_t b0, uint32_t b1) {
    asm volatile(
        "mma.sync.aligned.m16n8k16.row.col.f32.f16.f16.f32 "
        "{%0,%1,%2,%3},{%4,%5,%6,%7},{%8,%9},{%0,%1,%2,%3};\n"
        : "+f"(c[0]), "+f"(c[1]), "+f"(c[2]), "+f"(c[3])
        : "r"(a[0]), "r"(a[1]), "r"(a[2]), "r"(a[3]), "r"(b0), "r"(b1));
}
__device__ __forceinline__ void ldsm4(uint32_t& r0, uint32_t& r1,
                                      uint32_t& r2, uint32_t& r3, uint32_t a) {
    asm volatile("ldmatrix.sync.aligned.m8n8.x4.shared.b16 {%0,%1,%2,%3}, [%4];"
                 : "=r"(r0), "=r"(r1), "=r"(r2), "=r"(r3) : "r"(a));
}
__device__ __forceinline__ void ldsm4t(uint32_t& r0, uint32_t& r1,
                                       uint32_t& r2, uint32_t& r3, uint32_t a) {
    asm volatile("ldmatrix.sync.aligned.m8n8.x4.trans.shared.b16 {%0,%1,%2,%3}, [%4];"
                 : "=r"(r0), "=r"(r1), "=r"(r2), "=r"(r3) : "r"(a));
}
__device__ __forceinline__ void cp_async16(uint32_t smem_dst, const void* gsrc) {
    asm volatile("cp.async.cg.shared.global [%0], [%1], 16;\n"
                 :: "r"(smem_dst), "l"(gsrc));
}
__device__ __forceinline__ void cp_commit() {
    asm volatile("cp.async.commit_group;\n");
}
template <int N>
__device__ __forceinline__ void cp_wait() {
    asm volatile("cp.async.wait_group %0;\n" :: "n"(N));
}
__device__ __forceinline__ float fast_ex2(float x) {
    float r;
    asm("ex2.approx.f32 %0, %1;" : "=f"(r) : "f"(x));
    return r;
}
// Packed half2 exp2: convert two fp32 deltas to half2, one MUFU op for both.
__device__ __forceinline__ uint32_t ex2_h2(float a, float b) {
    __half2 h = __floats2half2_rn(a, b);
    uint32_t u = *reinterpret_cast<uint32_t*>(&h);
    uint32_t r;
    asm("ex2.approx.f16x2 %0, %1;" : "=r"(r) : "r"(u));
    return r;
}

// ---------------------------------------------------------------------------
// fp32 -> fp16 convert (one-shot)
// ---------------------------------------------------------------------------
__global__ void to_half(const float* __restrict__ in, __half* __restrict__ out,
                        int n4)
{
    int i = blockIdx.x * blockDim.x + threadIdx.x;
    if (i < n4) {
        float4 v = ((const float4*)in)[i];
        __half2* o = (__half2*)out + 2 * (size_t)i;
        o[0] = __floats2half2_rn(v.x, v.y);
        o[1] = __floats2half2_rn(v.z, v.w);
    }
}

// ---------------------------------------------------------------------------
// fp16 tensor-core GEMM + bias. BM=BN=128, BK=32, 8 warps (2x4),
// warp tile 64x32, m16n8k16, 4-stage cp.async ring (&3 slots), 2 CTAs/SM.
// (UNCHANGED from round 14 — proven at 192us / 44% tensor.)
// ---------------------------------------------------------------------------
#define AS2 40
#define BS2 136
#define G_STAGES 4
#define A_STGH (128 * AS2)       // halfs per A stage (5120)
#define B_STGH (32 * BS2)        // halfs per B stage (4352)
#define GEMM_SMEM ((G_STAGES * (A_STGH + B_STGH)) * 2)   // 75776 B

template <bool HALF_OUT>
__global__ void __launch_bounds__(256, 2)
gemm_fp16(int M, int N, int K,
          const __half* __restrict__ A,
          const __half* __restrict__ W,
          const float* __restrict__ bias,
          void* __restrict__ Cv)
{
    extern __shared__ __half dsm[];
    __half* As = dsm;
    __half* Bs = dsm + G_STAGES * A_STGH;
    const uint32_t as_u32 = (uint32_t)__cvta_generic_to_shared(As);
    const uint32_t bs_u32 = (uint32_t)__cvta_generic_to_shared(Bs);

    const int tid  = threadIdx.x;
    const int wid  = tid >> 5;
    const int lane = tid & 31;
    const int gid  = lane >> 2;
    const int tig  = lane & 3;
    const int wm   = wid >> 2;   // 0..1 -> 64 rows
    const int wn   = wid & 3;    // 0..3 -> 32 cols

    const __half* Ab = A + (size_t)blockIdx.y * 128 * K;
    const __half* Wb = W + (size_t)blockIdx.x * 128;

    const int aRow = tid >> 1;              // 0..127
    const int aC0  = (tid & 1) * 2;         // chunk 0..3 (16B each)
    const int bRow = tid >> 3;              // 0..31
    const int bC0  = (tid & 7) * 2;         // chunk 0..15

    const int j    = lane >> 3;             // matrix idx 0..3
    const int l7   = lane & 7;
    const int aLr  = (j & 1) * 8 + l7;      // A row-style
    const int aLc  = (j >> 1) * 8;
    const int bLk  = (j & 1) * 8 + l7;      // B trans k-row
    const int bLn  = (j >> 1) * 8;

    float c[4][4][4];
    #pragma unroll
    for (int i = 0; i < 4; i++)
        #pragma unroll
        for (int jj = 0; jj < 4; jj++)
            #pragma unroll
            for (int r = 0; r < 4; r++) c[i][jj][r] = 0.0f;

    const int T = K / 32;

    auto issue = [&](int kt, int s) {
        uint32_t ad = as_u32 + (uint32_t)(s * A_STGH + aRow * AS2) * 2;
        const __half* asrc = Ab + (size_t)aRow * K + kt * 32;
        #pragma unroll
        for (int i = 0; i < 2; i++)
            cp_async16(ad + (aC0 + i) * 16, asrc + (aC0 + i) * 8);
        uint32_t bd = bs_u32 + (uint32_t)(s * B_STGH + bRow * BS2) * 2;
        const __half* bsrc = Wb + (size_t)(kt * 32 + bRow) * N;
        #pragma unroll
        for (int i = 0; i < 2; i++)
            cp_async16(bd + (bC0 + i) * 16, bsrc + (bC0 + i) * 8);
        cp_commit();
    };

    issue(0, 0);
    issue(1, 1);
    issue(2, 2);

    for (int t = 0; t < T; t++) {
        if (t + 2 < T)      cp_wait<2>();
        else if (t + 1 < T) cp_wait<1>();
        else                cp_wait<0>();
        __syncthreads();
        if (t + 3 < T) issue(t + 3, (t + 3) & 3);

        const uint32_t abase = as_u32 + (uint32_t)((t & 3) * A_STGH) * 2;
        const uint32_t bbase = bs_u32 + (uint32_t)((t & 3) * B_STGH) * 2;

        #pragma unroll
        for (int kk = 0; kk < 32; kk += 16) {
            uint32_t a[4][4];
            #pragma unroll
            for (int mt = 0; mt < 4; mt++) {
                uint32_t ad = abase +
                    (uint32_t)((wm * 64 + mt * 16 + aLr) * AS2 + kk + aLc) * 2;
                ldsm4(a[mt][0], a[mt][1], a[mt][2], a[mt][3], ad);
            }
            uint32_t bg[2][4];
            #pragma unroll
            for (int g = 0; g < 2; g++) {
                uint32_t bd = bbase +
                    (uint32_t)((kk + bLk) * BS2 + wn * 32 + g * 16 + bLn) * 2;
                ldsm4t(bg[g][0], bg[g][1], bg[g][2], bg[g][3], bd);
            }
            #pragma unroll
            for (int mt = 0; mt < 4; mt++)
                #pragma unroll
                for (int g = 0; g < 2; g++) {
                    mma16(c[mt][2 * g],     a[mt], bg[g][0], bg[g][1]);
                    mma16(c[mt][2 * g + 1], a[mt], bg[g][2], bg[g][3]);
                }
        }
    }

    // Epilogue
    #pragma unroll
    for (int mt = 0; mt < 4; mt++) {
        const int r = blockIdx.y * 128 + wm * 64 + mt * 16 + gid;
        #pragma unroll
        for (int nt = 0; nt < 4; nt++) {
            const int col = blockIdx.x * 128 + wn * 32 + nt * 8 + 2 * tig;
            float2 bv = *(const float2*)&bias[col];
            if (HALF_OUT) {
                __half* C = (__half*)Cv;
                *(__half2*)&C[(size_t)(r    ) * N + col] =
                    __floats2half2_rn(c[mt][nt][0] + bv.x, c[mt][nt][1] + bv.y);
                *(__half2*)&C[(size_t)(r + 8) * N + col] =
                    __floats2half2_rn(c[mt][nt][2] + bv.x, c[mt][nt][3] + bv.y);
            } else {
                float* C = (float*)Cv;
                float2 o0, o1;
                o0.x = c[mt][nt][0] + bv.x; o0.y = c[mt][nt][1] + bv.y;
                o1.x = c[mt][nt][2] + bv.x; o1.y = c[mt][nt][3] + bv.y;
                *(float2*)&C[(size_t)(r    ) * N + col] = o0;
                *(float2*)&C[(size_t)(r + 8) * N + col] = o1;
            }
        }
    }
}

// ---------------------------------------------------------------------------
// fp16 tensor-core flash attention — 256 threads, 8 warps x 16 q-rows
// (Br=128, Bc=64), occupancy 2 => 16 warps/SM (2x round 14).
// m16n8k16, cp.async double-buffered K/V, dynamic smem 54KB.
// Base-2 softmax with ex2.approx.f16x2 (result IS fp16 P, stored directly).
// Layout: K[2][64*AT_S] | V[2][64*AT_S] | PQ[128*AT_S]
// ---------------------------------------------------------------------------
#define AT_S 72   // halfs per row (144B; %128B == 16 -> conflict-free)
#define KV_STGH (64 * AT_S)
#define ATTN_SMEM ((4 * KV_STGH + 128 * AT_S) * 2)   // 55296 B
#define SCALE_LOG2E 0.1803368801111244f   // 0.125 * log2(e)

__global__ void __launch_bounds__(256, 2)
attn_fp16(const __half* __restrict__ qkv, __half* __restrict__ y)
{
    extern __shared__ __half asm_[];
    __half* Ksm = asm_;
    __half* Vsm = asm_ + 2 * KV_STGH;
    __half* Pq  = asm_ + 4 * KV_STGH;
    const uint32_t k_u32 = (uint32_t)__cvta_generic_to_shared(Ksm);
    const uint32_t v_u32 = (uint32_t)__cvta_generic_to_shared(Vsm);
    const uint32_t p_u32 = (uint32_t)__cvta_generic_to_shared(Pq);

    const int b    = blockIdx.z;
    const int h    = blockIdx.y;
    const int q0   = blockIdx.x * 128;
    const int tid  = threadIdx.x;
    const int wid  = tid >> 5;          // 0..7 -> 16 q-rows each
    const int lane = tid & 31;
    const int gid  = lane >> 2;
    const int tig  = lane & 3;
    const int pr   = wid * 16 + gid;    // this thread's q-row (frag row 0)

    // cp.async maps (256 threads)
    const int qRow = tid >> 1;          // Q rows 0..127, 4 chunks each
    const int qC0  = (tid & 1) * 4;
    const int sRow = tid >> 2;          // K/V rows 0..63, 2 chunks each
    const int sC0  = (tid & 3) * 2;

    // ldmatrix lane components
    const int j   = lane >> 3;
    const int l7  = lane & 7;
    const int aLr = (j & 1) * 8 + l7;   // A-style (Q/P) row
    const int aLc = (j >> 1) * 8;
    const int nLr = (j >> 1) * 8 + l7;  // K non-trans n-row
    const int nLc = (j & 1) * 8;
    const int vLk = (j & 1) * 8 + l7;   // V trans key-row
    const int vLn = (j >> 1) * 8;

    auto issue_q = [&]() {
        const __half* src = qkv + ((size_t)(b * SEQ + q0 + qRow)) * (3 * DMODEL)
                          + h * HD;
        uint32_t qd = p_u32 + (uint32_t)(qRow * AT_S) * 2;
        #pragma unroll
        for (int i = 0; i < 4; i++)
            cp_async16(qd + (qC0 + i) * 16, src + (qC0 + i) * 8);
        cp_commit();
    };
    auto issue_kv = [&](int kt, int s) {
        const __half* src = qkv + ((size_t)(b * SEQ + kt + sRow)) * (3 * DMODEL)
                          + DMODEL + h * HD;
        uint32_t kd = k_u32 + (uint32_t)(s * KV_STGH + sRow * AT_S) * 2;
        uint32_t vd = v_u32 + (uint32_t)(s * KV_STGH + sRow * AT_S) * 2;
        #pragma unroll
        for (int i = 0; i < 2; i++) {
            cp_async16(kd + (sC0 + i) * 16, src + (sC0 + i) * 8);
            cp_async16(vd + (sC0 + i) * 16, src + DMODEL + (sC0 + i) * 8);
        }
        cp_commit();
    };

    issue_q();
    issue_kv(0, 0);
    cp_wait<0>();
    __syncthreads();

    // Q fragments resident (4 k16 slabs)
    uint32_t qa[4][4];
    #pragma unroll
    for (int sl = 0; sl < 4; sl++) {
        uint32_t ad = p_u32 +
            (uint32_t)((wid * 16 + aLr) * AT_S + sl * 16 + aLc) * 2;
        ldsm4(qa[sl][0], qa[sl][1], qa[sl][2], qa[sl][3], ad);
    }

    float o[8][4];
    #pragma unroll
    for (int n = 0; n < 8; n++)
        #pragma unroll
        for (int q = 0; q < 4; q++) o[n][q] = 0.0f;
    float m0 = -1e30f, m1 = -1e30f, l0 = 0.0f, l1 = 0.0f;

    const int NT = SEQ / 64;
    for (int t = 0; t < NT; t++) {
        if (t > 0) {
            cp_wait<0>();
            __syncthreads();
        }
        if (t + 1 < NT) issue_kv((t + 1) * 64, (t + 1) & 1);

        const uint32_t kb = k_u32 + (uint32_t)((t & 1) * KV_STGH) * 2;
        const uint32_t vb = v_u32 + (uint32_t)((t & 1) * KV_STGH) * 2;

        // ---- S = Q K^T ----
        float s[8][4];
        #pragma unroll
        for (int n = 0; n < 8; n++)
            #pragma unroll
            for (int q = 0; q < 4; q++) s[n][q] = 0.0f;
        #pragma unroll
        for (int sl = 0; sl < 4; sl++) {
            const int kk = sl * 16;
            #pragma unroll
            for (int g = 0; g < 4; g++) {
                uint32_t r0, r1, r2, r3;
                uint32_t kd = kb + (uint32_t)((g * 16 + nLr) * AT_S + kk + nLc) * 2;
                ldsm4(r0, r1, r2, r3, kd);
                mma16(s[2 * g],     qa[sl], r0, r1);
                mma16(s[2 * g + 1], qa[sl], r2, r3);
            }
        }

        // ---- online softmax (base-2, f16x2 exp), rows pr and pr+8 ----
        float mx0 = -1e30f, mx1 = -1e30f;
        #pragma unroll
        for (int n = 0; n < 8; n++) {
            s[n][0] *= SCALE_LOG2E; s[n][1] *= SCALE_LOG2E;
            s[n][2] *= SCALE_LOG2E; s[n][3] *= SCALE_LOG2E;
            mx0 = fmaxf(mx0, fmaxf(s[n][0], s[n][1]));
            mx1 = fmaxf(mx1, fmaxf(s[n][2], s[n][3]));
        }
        mx0 = fmaxf(mx0, __shfl_xor_sync(0xffffffffu, mx0, 1));
        mx0 = fmaxf(mx0, __shfl_xor_sync(0xffffffffu, mx0, 2));
        mx1 = fmaxf(mx1, __shfl_xor_sync(0xffffffffu, mx1, 1));
        mx1 = fmaxf(mx1, __shfl_xor_sync(0xffffffffu, mx1, 2));
        const float mn0 = fmaxf(m0, mx0);
        const float mn1 = fmaxf(m1, mx1);
        const float al0 = fast_ex2(m0 - mn0);
        const float al1 = fast_ex2(m1 - mn1);
        m0 = mn0; m1 = mn1;

        // exp2 in packed fp16; result IS fp16 P -> store directly
        float sum0 = 0.0f, sum1 = 0.0f;
        #pragma unroll
        for (int n = 0; n < 8; n++) {
            uint32_t p0 = ex2_h2(s[n][0] - mn0, s[n][1] - mn0);
            uint32_t p1 = ex2_h2(s[n][2] - mn1, s[n][3] - mn1);
            *(uint32_t*)&Pq[(pr    ) * AT_S + n * 8 + 2 * tig] = p0;
            *(uint32_t*)&Pq[(pr + 8) * AT_S + n * 8 + 2 * tig] = p1;
            float2 f0 = __half22float2(*reinterpret_cast<__half2*>(&p0));
            float2 f1 = __half22float2(*reinterpret_cast<__half2*>(&p1));
            sum0 += f0.x + f0.y;
            sum1 += f1.x + f1.y;
        }
        sum0 += __shfl_xor_sync(0xffffffffu, sum0, 1);
        sum0 += __shfl_xor_sync(0xffffffffu, sum0, 2);
        sum1 += __shfl_xor_sync(0xffffffffu, sum1, 1);
        sum1 += __shfl_xor_sync(0xffffffffu, sum1, 2);
        l0 = l0 * al0 + sum0;
        l1 = l1 * al1 + sum1;

        #pragma unroll
        for (int n = 0; n < 8; n++) {
            o[n][0] *= al0; o[n][1] *= al0;
            o[n][2] *= al1; o[n][3] *= al1;
        }
        __syncwarp();

        // ---- O += P @ V ----
        #pragma unroll
        for (int sl = 0; sl < 4; sl++) {
            const int kk = sl * 16;
            uint32_t pa[4];
            {
                uint32_t pd = p_u32 +
                    (uint32_t)((wid * 16 + aLr) * AT_S + kk + aLc) * 2;
                ldsm4(pa[0], pa[1], pa[2], pa[3], pd);
            }
            #pragma unroll
            for (int g = 0; g < 4; g++) {
                uint32_t r0, r1, r2, r3;
                uint32_t vd = vb + (uint32_t)((kk + vLk) * AT_S + g * 16 + vLn) * 2;
                ldsm4t(r0, r1, r2, r3, vd);
                mma16(o[2 * g],     pa, r0, r1);
                mma16(o[2 * g + 1], pa, r2, r3);
            }
        }
    }

    // ---- normalize + write y (fp16) ----
    const float i0 = 1.0f / l0;
    const float i1 = 1.0f / l1;
    __half* yp = y + ((size_t)(b * SEQ + q0 + pr)) * DMODEL + h * HD;
    #pragma unroll
    for (int n = 0; n < 8; n++) {
        const int cc = n * 8 + 2 * tig;
        *(__half2*)&yp[cc] = __floats2half2_rn(o[n][0] * i0, o[n][1] * i0);
        *(__half2*)&yp[8 * DMODEL + cc] =
            __floats2half2_rn(o[n][2] * i1, o[n][3] * i1);
    }
}

// ---------------------------------------------------------------------------
// Launch
// ---------------------------------------------------------------------------
extern "C" void kernel_launch(void* const* d_in, const int* in_sizes, int n_in,
                              void* d_out, int out_size)
{
    const float* x     = (const float*)d_in[0];
    const float* Wqkv  = (const float*)d_in[1];
    const float* bqkv  = (const float*)d_in[2];
    const float* Wproj = (const float*)d_in[3];
    const float* bproj = (const float*)d_in[4];
    float* out = (float*)d_out;

    __half *qkv = nullptr, *y = nullptr, *xh = nullptr, *wq = nullptr, *wp = nullptr;
    cudaGetSymbolAddress((void**)&qkv, g_qkv);
    cudaGetSymbolAddress((void**)&y,   g_y);
    cudaGetSymbolAddress((void**)&xh,  g_x);
    cudaGetSymbolAddress((void**)&wq,  g_wq);
    cudaGetSymbolAddress((void**)&wp,  g_wp);

    cudaFuncSetAttribute(gemm_fp16<true>,
                         cudaFuncAttributeMaxDynamicSharedMemorySize, GEMM_SMEM);
    cudaFuncSetAttribute(gemm_fp16<false>,
                         cudaFuncAttributeMaxDynamicSharedMemorySize, GEMM_SMEM);
    cudaFuncSetAttribute(attn_fp16,
                         cudaFuncAttributeMaxDynamicSharedMemorySize, ATTN_SMEM);

    // 0) convert inputs/weights to fp16
    {
        int n4;
        n4 = MTOT * DMODEL / 4;
        to_half<<<(n4 + 255) / 256, 256>>>(x, xh, n4);
        n4 = DMODEL * 3 * DMODEL / 4;
        to_half<<<(n4 + 255) / 256, 256>>>(Wqkv, wq, n4);
        n4 = DMODEL * DMODEL / 4;
        to_half<<<(n4 + 255) / 256, 256>>>(Wproj, wp, n4);
    }

    // 1) QKV projection -> fp16 qkv
    gemm_fp16<true><<<dim3(3 * DMODEL / 128, MTOT / 128), 256, GEMM_SMEM>>>(
        MTOT, 3 * DMODEL, DMODEL, xh, wq, bqkv, qkv);

    // 2) flash attention -> fp16 y  (256 threads, Br=128)
    attn_fp16<<<dim3(SEQ / 128, NHEAD, BATCH), 256, ATTN_SMEM>>>(qkv, y);

    // 3) output projection -> fp32 out
    gemm_fp16<false><<<dim3(DMODEL / 128, MTOT / 128), 256, GEMM_SMEM>>>(
        MTOT, DMODEL, DMODEL, y, wp, bproj, out);
}